// round 8
// baseline (speedup 1.0000x reference)
#include <cuda_runtime.h>

#define T_STEPS 64
#define N_NODES 20000
#define NW2     1184   // 148 blocks x 8 warps, 2 warps per SMSP

__device__ float g_scratch[T_STEPS * NW2];

typedef unsigned long long ull;

__device__ __forceinline__ ull pack2(float v) {
    ull r; asm("mov.b64 %0, {%1, %1};" : "=l"(r) : "f"(v)); return r;
}
__device__ __forceinline__ void fma2(ull &acc, ull a, ull b) {
    asm("fma.rn.f32x2 %0, %1, %2, %0;" : "+l"(acc) : "l"(a), "l"(b));
}
__device__ __forceinline__ void unpack2(ull v, float &a, float &b) {
    asm("mov.b64 {%0, %1}, %2;" : "=f"(a), "=f"(b) : "l"(v));
}
__device__ __forceinline__ float tanha(float v) {
    float r; asm("tanh.approx.f32 %0, %1;" : "=f"(r) : "f"(v)); return r;
}
__device__ __forceinline__ float sigm(float v) {
    return fmaf(0.5f, tanha(0.5f * v), 0.5f);
}
__device__ __forceinline__ float lrelu(float v) { return fmaxf(v, 0.01f * v); }

struct SW {
    float z[40 * 32];   // rows 0..7 = Wx*, 8..39 = Wh*
    float r[40 * 32];
    float h[40 * 32];
    float cbz[32], cbr[32], cbh[32], w1[32];
};

// 8-lane node groups: lane = grp*8 + sl; thread owns h-cols [sl*4, sl*4+4) of
// its group's node. One warp-pass = 4 nodes. V passes per warp.
template<int V>
__device__ __forceinline__ void gru_warp(
    const SW* __restrict__ sw, const float* __restrict__ x,
    const float* __restrict__ h0, const float* __restrict__ W2,
    float b1s, float* __restrict__ out, int out_size, int pass_start, int gw)
{
    const int lane = threadIdx.x & 31;
    const int grp  = lane >> 3;
    const int sl   = lane & 7;
    const int gb8  = lane & 24;    // group base lane
    const int c0   = sl * 4;       // first owned h-col

    int   node[V];
    float h4[V][4], w2r[V];
#pragma unroll
    for (int u = 0; u < V; u++) {
        node[u] = (pass_start + u) * 4 + grp;
#pragma unroll
        for (int i = 0; i < 4; i++) h4[u][i] = h0[node[u] * 32 + c0 + i];
        w2r[u] = W2[node[u]];
    }
    float w1r[4];
#pragma unroll
    for (int i = 0; i < 4; i++) w1r[i] = sw->w1[c0 + i];

    ull bz[2], br[2], bh[2];
#pragma unroll
    for (int i = 0; i < 2; i++) {
        bz[i] = ((const ull*)&sw->cbz[c0])[i];
        br[i] = ((const ull*)&sw->cbr[c0])[i];
        bh[i] = ((const ull*)&sw->cbh[c0])[i];
    }

#pragma unroll 1
    for (int t = 0; t < T_STEPS; ++t) {
        float st = 0.0f;
        const float* xb = x + (size_t)t * (N_NODES * 8);

#pragma unroll
        for (int u = 0; u < V; u++) {
            // this lane's x feature (feature index = sl) for its group's node
            const float xv = xb[(size_t)node[u] * 8 + sl];

            // ---------- phase 1: z, r ----------
            ull az[2] = {bz[0], bz[1]};
            ull ar[2] = {br[0], br[1]};
#pragma unroll 1
            for (int sp = 0; sp < 8; sp++) {
#pragma unroll
                for (int c = 0; c < 4; c++) {
                    const int k = 8 + sp * 4 + c;
                    const ulonglong2 wz = *(const ulonglong2*)&sw->z[k * 32 + c0];
                    const ulonglong2 wr = *(const ulonglong2*)&sw->r[k * 32 + c0];
                    ull m = pack2(__shfl_sync(0xffffffffu, h4[u][c], gb8 + sp));
                    fma2(az[0], m, wz.x); fma2(az[1], m, wz.y);
                    fma2(ar[0], m, wr.x); fma2(ar[1], m, wr.y);
                }
            }
#pragma unroll
            for (int k = 0; k < 8; k++) {
                const ulonglong2 wz = *(const ulonglong2*)&sw->z[k * 32 + c0];
                const ulonglong2 wr = *(const ulonglong2*)&sw->r[k * 32 + c0];
                ull m = pack2(__shfl_sync(0xffffffffu, xv, gb8 + k));
                fma2(az[0], m, wz.x); fma2(az[1], m, wz.y);
                fma2(ar[0], m, wr.x); fma2(ar[1], m, wr.y);
            }

            // ---------- gates ----------
            float zz[4], gg[4];
#pragma unroll
            for (int i = 0; i < 2; i++) {
                float a, b;
                unpack2(az[i], a, b);
                zz[2*i] = sigm(a); zz[2*i+1] = sigm(b);
                unpack2(ar[i], a, b);
                gg[2*i]   = h4[u][2*i]   * sigm(a);
                gg[2*i+1] = h4[u][2*i+1] * sigm(b);
            }

            // ---------- phase 2: candidate ----------
            ull ah[2] = {bh[0], bh[1]};
#pragma unroll
            for (int k = 0; k < 8; k++) {
                const ulonglong2 wh = *(const ulonglong2*)&sw->h[k * 32 + c0];
                ull m = pack2(__shfl_sync(0xffffffffu, xv, gb8 + k));
                fma2(ah[0], m, wh.x); fma2(ah[1], m, wh.y);
            }
#pragma unroll 1
            for (int sp = 0; sp < 8; sp++) {
#pragma unroll
                for (int c = 0; c < 4; c++) {
                    const int k = 8 + sp * 4 + c;
                    const ulonglong2 wh = *(const ulonglong2*)&sw->h[k * 32 + c0];
                    ull m = pack2(__shfl_sync(0xffffffffu, gg[c], gb8 + sp));
                    fma2(ah[0], m, wh.x); fma2(ah[1], m, wh.y);
                }
            }

            // ---------- update + readout partial ----------
            float p = 0.0f;
#pragma unroll
            for (int i = 0; i < 2; i++) {
                float a, b;
                unpack2(ah[i], a, b);
                float t0 = tanha(a), t1 = tanha(b);
                float hn0 = t0 + zz[2*i]   * (h4[u][2*i]   - t0);
                float hn1 = t1 + zz[2*i+1] * (h4[u][2*i+1] - t1);
                h4[u][2*i] = hn0; h4[u][2*i+1] = hn1;
                p = fmaf(lrelu(hn0), w1r[2*i],   p);
                p = fmaf(lrelu(hn1), w1r[2*i+1], p);
            }
            // sum over the 8 sub-lanes of this node group
            p += __shfl_xor_sync(0xffffffffu, p, 1);
            p += __shfl_xor_sync(0xffffffffu, p, 2);
            p += __shfl_xor_sync(0xffffffffu, p, 4);
            st += lrelu(p + b1s) * w2r[u];
        }

        // sum over the 4 groups of the warp
        st += __shfl_xor_sync(0xffffffffu, st, 8);
        st += __shfl_xor_sync(0xffffffffu, st, 16);
        if (lane == 0) g_scratch[t * NW2 + gw] = st;
    }

    if (out_size >= N_NODES * 32) {
        const int hoff = out_size - N_NODES * 32;
#pragma unroll
        for (int u = 0; u < V; u++)
#pragma unroll
            for (int i = 0; i < 4; i++)
                out[hoff + node[u] * 32 + c0 + i] = h4[u][i];
    }
}

__global__ void __launch_bounds__(256, 1)
gru_kernel(const float* __restrict__ x, const float* __restrict__ h0,
           const float* __restrict__ Wxz, const float* __restrict__ bxz,
           const float* __restrict__ Whz, const float* __restrict__ bhz,
           const float* __restrict__ Wxr, const float* __restrict__ bxr,
           const float* __restrict__ Whr, const float* __restrict__ bhr,
           const float* __restrict__ Wxh, const float* __restrict__ bxh,
           const float* __restrict__ Whh, const float* __restrict__ bhh,
           const float* __restrict__ W1,  const float* __restrict__ b1,
           const float* __restrict__ W2,
           float* __restrict__ out, int out_size)
{
    __shared__ __align__(16) SW sw;

    for (int i = threadIdx.x; i < 8 * 32; i += 256) {
        sw.z[i] = Wxz[i]; sw.r[i] = Wxr[i]; sw.h[i] = Wxh[i];
    }
    for (int i = threadIdx.x; i < 32 * 32; i += 256) {
        sw.z[256 + i] = Whz[i]; sw.r[256 + i] = Whr[i]; sw.h[256 + i] = Whh[i];
    }
    if (threadIdx.x < 32) {
        int i = threadIdx.x;
        sw.cbz[i] = bxz[i] + bhz[i];
        sw.cbr[i] = bxr[i] + bhr[i];
        sw.cbh[i] = bxh[i] + bhh[i];
        sw.w1[i]  = W1[i];
    }
    __syncthreads();

    const int w  = threadIdx.x >> 5;   // warp in block, 0..7; SMSP = w & 3
    const int b  = blockIdx.x;
    const int gw = b * 8 + w;
    const float b1s = b1[0];

    // 5000 passes of 4 nodes. Blocks 0..65: warps 0-3 carry 5 passes, warps
    // 4-7 carry 4 (SMSP pairs {5,4} -> 36 nodes). Blocks 66..147: all 4.
    if (b < 66) {
        if (w < 4) {
            gru_warp<5>(&sw, x, h0, W2, b1s, out, out_size, 36 * b + 5 * w, gw);
        } else {
            gru_warp<4>(&sw, x, h0, W2, b1s, out, out_size,
                        36 * b + 20 + 4 * (w - 4), gw);
        }
    } else {
        gru_warp<4>(&sw, x, h0, W2, b1s, out, out_size,
                    2376 + 32 * (b - 66) + 4 * w, gw);
    }
}

__global__ void reduce_out(const float* __restrict__ b2,
                           float* __restrict__ out, int out_size)
{
    const int t = blockIdx.x;
    float s = 0.0f;
    for (int w = threadIdx.x; w < NW2; w += 256)
        s += g_scratch[t * NW2 + w];
#pragma unroll
    for (int o = 16; o; o >>= 1) s += __shfl_xor_sync(0xffffffffu, s, o);
    __shared__ float red[8];
    if ((threadIdx.x & 31) == 0) red[threadIdx.x >> 5] = s;
    __syncthreads();
    if (threadIdx.x < 8) {
        s = red[threadIdx.x];
#pragma unroll
        for (int o = 4; o; o >>= 1) s += __shfl_xor_sync(0x000000ffu, s, o);
        if (threadIdx.x == 0) {
            bool wr = (out_size >= T_STEPS + N_NODES * 32) || (out_size < N_NODES * 32);
            if (wr && t < out_size) out[t] = s + b2[0];
        }
    }
}

extern "C" void kernel_launch(void* const* d_in, const int* in_sizes, int n_in,
                              void* d_out, int out_size) {
    const float* x   = (const float*)d_in[0];
    const float* h0  = (const float*)d_in[3];
    const float* Wxz = (const float*)d_in[4];
    const float* bxz = (const float*)d_in[5];
    const float* Whz = (const float*)d_in[6];
    const float* bhz = (const float*)d_in[7];
    const float* Wxr = (const float*)d_in[8];
    const float* bxr = (const float*)d_in[9];
    const float* Whr = (const float*)d_in[10];
    const float* bhr = (const float*)d_in[11];
    const float* Wxh = (const float*)d_in[12];
    const float* bxh = (const float*)d_in[13];
    const float* Whh = (const float*)d_in[14];
    const float* bhh = (const float*)d_in[15];
    const float* W1  = (const float*)d_in[16];
    const float* b1  = (const float*)d_in[17];
    const float* W2  = (const float*)d_in[18];
    const float* b2  = (const float*)d_in[19];
    float* out = (float*)d_out;

    gru_kernel<<<148, 256>>>(x, h0, Wxz, bxz, Whz, bhz, Wxr, bxr, Whr, bhr,
                             Wxh, bxh, Whh, bhh, W1, b1, W2, out, out_size);
    reduce_out<<<T_STEPS, 256>>>(b2, out, out_size);
}

// round 9
// speedup vs baseline: 2.2162x; 2.2162x over previous
#include <cuda_runtime.h>

#define T_STEPS 64
#define N_NODES 20000
#define NW2     1184   // 148 blocks x 8 warps, 2 warps per SMSP

__device__ float g_scratch[T_STEPS * NW2];

typedef unsigned long long ull;

__device__ __forceinline__ ull pack2(float v) {
    ull r; asm("mov.b64 %0, {%1, %1};" : "=l"(r) : "f"(v)); return r;
}
__device__ __forceinline__ void fma2(ull &acc, ull a, ull b) {
    asm("fma.rn.f32x2 %0, %1, %2, %0;" : "+l"(acc) : "l"(a), "l"(b));
}
__device__ __forceinline__ void unpack2(ull v, float &a, float &b) {
    asm("mov.b64 {%0, %1}, %2;" : "=f"(a), "=f"(b) : "l"(v));
}
__device__ __forceinline__ float tanha(float v) {
    float r; asm("tanh.approx.f32 %0, %1;" : "=f"(r) : "f"(v)); return r;
}
__device__ __forceinline__ float sigm(float v) {
    return fmaf(0.5f, tanha(0.5f * v), 0.5f);
}
__device__ __forceinline__ float lrelu(float v) { return fmaxf(v, 0.01f * v); }

struct SW {
    float z[40 * 32];   // rows 0..7 = Wx*, 8..39 = Wh*
    float r[40 * 32];
    float h[40 * 32];
    float cbz[32], cbr[32], cbh[32], w1[32];
};

// 8-lane node groups: lane = grp*8 + sl. Thread owns h-cols [sl*4, sl*4+4).
// One pass = 4 nodes (one per group). V passes per warp; weight LDS shared
// across all V passes (loads hoisted OUT of the u loop — R8's bug fixed).
template<int V>
__device__ __forceinline__ void gru_warp(
    const SW* __restrict__ sw, const float* __restrict__ x,
    const float* __restrict__ h0, const float* __restrict__ W2,
    float b1s, float* __restrict__ out, int out_size, int pass_start, int gw)
{
    const int lane = threadIdx.x & 31;
    const int grp  = lane >> 3;
    const int sl   = lane & 7;
    const int gb8  = lane & 24;    // group base lane
    const int c0   = sl * 4;       // first owned h-col

    int   node[V];
    float h4[V][4], w2r[V];
#pragma unroll
    for (int u = 0; u < V; u++) {
        node[u] = (pass_start + u) * 4 + grp;
#pragma unroll
        for (int i = 0; i < 4; i++) h4[u][i] = h0[node[u] * 32 + c0 + i];
        w2r[u] = W2[node[u]];
    }
    float w1r[4];
#pragma unroll
    for (int i = 0; i < 4; i++) w1r[i] = sw->w1[c0 + i];

    ull bz[2], br[2], bh[2];
#pragma unroll
    for (int i = 0; i < 2; i++) {
        bz[i] = ((const ull*)&sw->cbz[c0])[i];
        br[i] = ((const ull*)&sw->cbr[c0])[i];
        bh[i] = ((const ull*)&sw->cbh[c0])[i];
    }

#pragma unroll 1
    for (int t = 0; t < T_STEPS; ++t) {
        const float* xb = x + (size_t)t * (N_NODES * 8);
        float xv[V];
#pragma unroll
        for (int u = 0; u < V; u++)
            xv[u] = xb[(size_t)node[u] * 8 + sl];   // lane sl holds feature sl

        // ---------- phase 1: z, r pre-activations ----------
        ull az[V][2], ar[V][2];
#pragma unroll
        for (int u = 0; u < V; u++) {
            az[u][0] = bz[0]; az[u][1] = bz[1];
            ar[u][0] = br[0]; ar[u][1] = br[1];
        }
        // h-part: weights loaded once per (sp,c), shared over all V passes
#pragma unroll 1
        for (int sp = 0; sp < 8; sp++) {
#pragma unroll
            for (int c = 0; c < 4; c++) {
                const int k = 8 + sp * 4 + c;
                const ulonglong2 wz = *(const ulonglong2*)&sw->z[k * 32 + c0];
                const ulonglong2 wr = *(const ulonglong2*)&sw->r[k * 32 + c0];
#pragma unroll
                for (int u = 0; u < V; u++) {
                    ull m = pack2(__shfl_sync(0xffffffffu, h4[u][c], gb8 + sp));
                    fma2(az[u][0], m, wz.x); fma2(az[u][1], m, wz.y);
                    fma2(ar[u][0], m, wr.x); fma2(ar[u][1], m, wr.y);
                }
            }
        }
        // x-part
#pragma unroll
        for (int k = 0; k < 8; k++) {
            const ulonglong2 wz = *(const ulonglong2*)&sw->z[k * 32 + c0];
            const ulonglong2 wr = *(const ulonglong2*)&sw->r[k * 32 + c0];
#pragma unroll
            for (int u = 0; u < V; u++) {
                ull m = pack2(__shfl_sync(0xffffffffu, xv[u], gb8 + k));
                fma2(az[u][0], m, wz.x); fma2(az[u][1], m, wz.y);
                fma2(ar[u][0], m, wr.x); fma2(ar[u][1], m, wr.y);
            }
        }

        // ---------- gates (az/ar die; zz/gg born) ----------
        float zz[V][4], gg[V][4];
#pragma unroll
        for (int u = 0; u < V; u++)
#pragma unroll
            for (int i = 0; i < 2; i++) {
                float a, b;
                unpack2(az[u][i], a, b);
                zz[u][2*i] = sigm(a); zz[u][2*i+1] = sigm(b);
                unpack2(ar[u][i], a, b);
                gg[u][2*i]   = h4[u][2*i]   * sigm(a);
                gg[u][2*i+1] = h4[u][2*i+1] * sigm(b);
            }

        // ---------- phase 2: candidate ----------
        ull ah[V][2];
#pragma unroll
        for (int u = 0; u < V; u++) { ah[u][0] = bh[0]; ah[u][1] = bh[1]; }
        // x-part (xv dies here)
#pragma unroll
        for (int k = 0; k < 8; k++) {
            const ulonglong2 wh = *(const ulonglong2*)&sw->h[k * 32 + c0];
#pragma unroll
            for (int u = 0; u < V; u++) {
                ull m = pack2(__shfl_sync(0xffffffffu, xv[u], gb8 + k));
                fma2(ah[u][0], m, wh.x); fma2(ah[u][1], m, wh.y);
            }
        }
        // h-part
#pragma unroll 1
        for (int sp = 0; sp < 8; sp++) {
#pragma unroll
            for (int c = 0; c < 4; c++) {
                const int k = 8 + sp * 4 + c;
                const ulonglong2 wh = *(const ulonglong2*)&sw->h[k * 32 + c0];
#pragma unroll
                for (int u = 0; u < V; u++) {
                    ull m = pack2(__shfl_sync(0xffffffffu, gg[u][c], gb8 + sp));
                    fma2(ah[u][0], m, wh.x); fma2(ah[u][1], m, wh.y);
                }
            }
        }

        // ---------- update + fused readout ----------
        float st = 0.0f;
#pragma unroll
        for (int u = 0; u < V; u++) {
            float p = 0.0f;
#pragma unroll
            for (int i = 0; i < 2; i++) {
                float a, b;
                unpack2(ah[u][i], a, b);
                float t0 = tanha(a), t1 = tanha(b);
                float hn0 = t0 + zz[u][2*i]   * (h4[u][2*i]   - t0);
                float hn1 = t1 + zz[u][2*i+1] * (h4[u][2*i+1] - t1);
                h4[u][2*i] = hn0; h4[u][2*i+1] = hn1;
                p = fmaf(lrelu(hn0), w1r[2*i],   p);
                p = fmaf(lrelu(hn1), w1r[2*i+1], p);
            }
            p += __shfl_xor_sync(0xffffffffu, p, 1);
            p += __shfl_xor_sync(0xffffffffu, p, 2);
            p += __shfl_xor_sync(0xffffffffu, p, 4);
            st += lrelu(p + b1s) * w2r[u];
        }
        st += __shfl_xor_sync(0xffffffffu, st, 8);
        st += __shfl_xor_sync(0xffffffffu, st, 16);
        if (lane == 0) g_scratch[t * NW2 + gw] = st;
    }

    if (out_size >= N_NODES * 32) {
        const int hoff = out_size - N_NODES * 32;
#pragma unroll
        for (int u = 0; u < V; u++)
#pragma unroll
            for (int i = 0; i < 4; i++)
                out[hoff + node[u] * 32 + c0 + i] = h4[u][i];
    }
}

__global__ void __launch_bounds__(256, 1)
gru_kernel(const float* __restrict__ x, const float* __restrict__ h0,
           const float* __restrict__ Wxz, const float* __restrict__ bxz,
           const float* __restrict__ Whz, const float* __restrict__ bhz,
           const float* __restrict__ Wxr, const float* __restrict__ bxr,
           const float* __restrict__ Whr, const float* __restrict__ bhr,
           const float* __restrict__ Wxh, const float* __restrict__ bxh,
           const float* __restrict__ Whh, const float* __restrict__ bhh,
           const float* __restrict__ W1,  const float* __restrict__ b1,
           const float* __restrict__ W2,
           float* __restrict__ out, int out_size)
{
    __shared__ __align__(16) SW sw;

    for (int i = threadIdx.x; i < 8 * 32; i += 256) {
        sw.z[i] = Wxz[i]; sw.r[i] = Wxr[i]; sw.h[i] = Wxh[i];
    }
    for (int i = threadIdx.x; i < 32 * 32; i += 256) {
        sw.z[256 + i] = Whz[i]; sw.r[256 + i] = Whr[i]; sw.h[256 + i] = Whh[i];
    }
    if (threadIdx.x < 32) {
        int i = threadIdx.x;
        sw.cbz[i] = bxz[i] + bhz[i];
        sw.cbr[i] = bxr[i] + bhr[i];
        sw.cbh[i] = bxh[i] + bhh[i];
        sw.w1[i]  = W1[i];
    }
    __syncthreads();

    const int w  = threadIdx.x >> 5;   // warp in block; SMSP = w & 3
    const int b  = blockIdx.x;
    const int gw = b * 8 + w;
    const float b1s = b1[0];

    // 5000 passes of 4 nodes. Blocks 0..65: warps 0-3 carry 5 passes,
    // warps 4-7 carry 4 (each SMSP pair totals 9). Blocks 66..147: all 4.
    if (b < 66) {
        if (w < 4) {
            gru_warp<5>(&sw, x, h0, W2, b1s, out, out_size, 36 * b + 5 * w, gw);
        } else {
            gru_warp<4>(&sw, x, h0, W2, b1s, out, out_size,
                        36 * b + 20 + 4 * (w - 4), gw);
        }
    } else {
        gru_warp<4>(&sw, x, h0, W2, b1s, out, out_size,
                    2376 + 32 * (b - 66) + 4 * w, gw);
    }
}

__global__ void reduce_out(const float* __restrict__ b2,
                           float* __restrict__ out, int out_size)
{
    const int t = blockIdx.x;
    float s = 0.0f;
    for (int w = threadIdx.x; w < NW2; w += 256)
        s += g_scratch[t * NW2 + w];
#pragma unroll
    for (int o = 16; o; o >>= 1) s += __shfl_xor_sync(0xffffffffu, s, o);
    __shared__ float red[8];
    if ((threadIdx.x & 31) == 0) red[threadIdx.x >> 5] = s;
    __syncthreads();
    if (threadIdx.x < 8) {
        s = red[threadIdx.x];
#pragma unroll
        for (int o = 4; o; o >>= 1) s += __shfl_xor_sync(0x000000ffu, s, o);
        if (threadIdx.x == 0) {
            bool wr = (out_size >= T_STEPS + N_NODES * 32) || (out_size < N_NODES * 32);
            if (wr && t < out_size) out[t] = s + b2[0];
        }
    }
}

extern "C" void kernel_launch(void* const* d_in, const int* in_sizes, int n_in,
                              void* d_out, int out_size) {
    const float* x   = (const float*)d_in[0];
    const float* h0  = (const float*)d_in[3];
    const float* Wxz = (const float*)d_in[4];
    const float* bxz = (const float*)d_in[5];
    const float* Whz = (const float*)d_in[6];
    const float* bhz = (const float*)d_in[7];
    const float* Wxr = (const float*)d_in[8];
    const float* bxr = (const float*)d_in[9];
    const float* Whr = (const float*)d_in[10];
    const float* bhr = (const float*)d_in[11];
    const float* Wxh = (const float*)d_in[12];
    const float* bxh = (const float*)d_in[13];
    const float* Whh = (const float*)d_in[14];
    const float* bhh = (const float*)d_in[15];
    const float* W1  = (const float*)d_in[16];
    const float* b1  = (const float*)d_in[17];
    const float* W2  = (const float*)d_in[18];
    const float* b2  = (const float*)d_in[19];
    float* out = (float*)d_out;

    gru_kernel<<<148, 256>>>(x, h0, Wxz, bxz, Whz, bhz, Wxr, bxr, Whr, bhr,
                             Wxh, bxh, Whh, bhh, W1, b1, W2, out, out_size);
    reduce_out<<<T_STEPS, 256>>>(b2, out, out_size);
}

// round 12
// speedup vs baseline: 2.8173x; 1.2712x over previous
#include <cuda_runtime.h>
#include <cuda_bf16.h>
#include <cstdint>

#define T_STEPS 64
#define N_NODES 20000
#define NTILES_TOT 1250     // 16 nodes per tile
#define NWARPS     1184     // 148 x 8
#define NEXTRA     66       // blocks 0..65, warp 0 takes tile 1184+b

__device__ float g_scratch[T_STEPS * NTILES_TOT];

__device__ __forceinline__ float tanha(float v) {
    float r; asm("tanh.approx.f32 %0, %1;" : "=f"(r) : "f"(v)); return r;
}
__device__ __forceinline__ float sigm(float v) { return fmaf(0.5f, tanha(0.5f * v), 0.5f); }
__device__ __forceinline__ float lrelu(float v) { return fmaxf(v, 0.01f * v); }
__device__ __forceinline__ float bfr(float v) { return __bfloat162float(__float2bfloat16(v)); }
__device__ __forceinline__ uint32_t bf2(float lo, float hi) {  // low half = lo (element k), high = hi (k+1)
    uint32_t r; asm("cvt.rn.bf16x2.f32 %0, %1, %2;" : "=r"(r) : "f"(hi), "f"(lo)); return r;
}
__device__ __forceinline__ uint32_t s2u(const void* p) {
    uint32_t a; asm("{ .reg .u64 t; cvta.to.shared.u64 t, %1; cvt.u32.u64 %0, t; }" : "=r"(a) : "l"(p));
    return a;
}
__device__ __forceinline__ void mma16816(float* c, const uint32_t* a, const uint32_t* b) {
    asm volatile("mma.sync.aligned.m16n8k16.row.col.f32.bf16.bf16.f32 "
        "{%0,%1,%2,%3}, {%4,%5,%6,%7}, {%8,%9}, {%0,%1,%2,%3};"
        : "+f"(c[0]), "+f"(c[1]), "+f"(c[2]), "+f"(c[3])
        : "r"(a[0]), "r"(a[1]), "r"(a[2]), "r"(a[3]), "r"(b[0]), "r"(b[1]));
}
__device__ __forceinline__ void ldsm2(uint32_t* d, uint32_t addr) {
    asm volatile("ldmatrix.sync.aligned.m8n8.x2.shared.b16 {%0,%1}, [%2];"
        : "=r"(d[0]), "=r"(d[1]) : "r"(addr));
}

// smem weight stores: rows [n][k], 56 halves (112B) stride
__shared__ __nv_bfloat16 sW1h[96 * 56], sW1l[96 * 56], sW2h[32 * 56], sW2l[32 * 56];

// ldmatrix x2 address: tile pair (klow, khigh) for n-block j, k-chunk c
__device__ __forceinline__ uint32_t boff(int j, int c, int lane) {
    return (uint32_t)((8 * j + (lane & 7)) * 112 + c * 32 + ((lane >> 3) & 1) * 16);
}

template<int NT>
__device__ void run_tiles(const int* tiles,
    const float* __restrict__ x, const float* __restrict__ h0,
    const float* __restrict__ W1, float b1s, const float* __restrict__ W2,
    float* __restrict__ out, int out_size, int lane,
    uint32_t w1h, uint32_t w1l, uint32_t w2h, uint32_t w2l)
{
    // per-thread slot s (0..7): dim(s) = 2*(lane&3) + 8*(s>>1) + (s&1)
    float w1s[8];
#pragma unroll
    for (int s = 0; s < 8; s++) w1s[s] = W1[2 * (lane & 3) + 8 * (s >> 1) + (s & 1)];

    int   n0_[NT], n1_[NT];
    float h[NT][2][8], w2a[NT], w2b[NT];
#pragma unroll
    for (int u = 0; u < NT; u++) {
        n0_[u] = tiles[u] * 16 + (lane >> 2);
        n1_[u] = n0_[u] + 8;
#pragma unroll
        for (int s = 0; s < 8; s++) {
            int d = 2 * (lane & 3) + 8 * (s >> 1) + (s & 1);
            h[u][0][s] = h0[n0_[u] * 32 + d];
            h[u][1][s] = h0[n1_[u] * 32 + d];
        }
        w2a[u] = W2[n0_[u]]; w2b[u] = W2[n1_[u]];
    }
    const uint32_t biasreg = ((lane & 3) == 0) ? 0x00003F80u : 0u;  // bf16 1.0 at k==8

#pragma unroll 1
    for (int t = 0; t < T_STEPS; ++t) {
#pragma unroll 1
        for (int u = 0; u < NT; u++) {
            // ---- A chunk0: x + bias ----
            const float* xb = x + (size_t)t * (N_NODES * 8);
            float2 xa = *(const float2*)(xb + (size_t)n0_[u] * 8 + 2 * (lane & 3));
            float2 xc = *(const float2*)(xb + (size_t)n1_[u] * 8 + 2 * (lane & 3));
            uint32_t A0h[4], A0l[4];
            A0h[0] = bf2(xa.x, xa.y); A0l[0] = bf2(xa.x - bfr(xa.x), xa.y - bfr(xa.y));
            A0h[1] = bf2(xc.x, xc.y); A0l[1] = bf2(xc.x - bfr(xc.x), xc.y - bfr(xc.y));
            A0h[2] = biasreg; A0h[3] = biasreg; A0l[2] = 0; A0l[3] = 0;
            // ---- A chunks 1,2 from h ----
            uint32_t A1h[4], A1l[4], A2h[4], A2l[4];
#pragma unroll
            for (int i = 0; i < 2; i++) {
                float a0 = h[u][i][0], a1 = h[u][i][1], a2 = h[u][i][2], a3 = h[u][i][3];
                A1h[i]     = bf2(a0, a1); A1l[i]     = bf2(a0 - bfr(a0), a1 - bfr(a1));
                A1h[i + 2] = bf2(a2, a3); A1l[i + 2] = bf2(a2 - bfr(a2), a3 - bfr(a3));
                float c0 = h[u][i][4], c1 = h[u][i][5], c2 = h[u][i][6], c3 = h[u][i][7];
                A2h[i]     = bf2(c0, c1); A2l[i]     = bf2(c0 - bfr(c0), c1 - bfr(c1));
                A2h[i + 2] = bf2(c2, c3); A2l[i + 2] = bf2(c2 - bfr(c2), c3 - bfr(c3));
            }

            // ---- MMA1: 12 n-tiles ----
            float zz[2][8], gg[2][8], candC[4][4];
#pragma unroll
            for (int j = 0; j < 12; j++) {
                float C[4] = {0.f, 0.f, 0.f, 0.f};
#pragma unroll
                for (int c = 0; c < 3; c++) {
                    uint32_t bh[2], bl[2];
                    ldsm2(bh, w1h + boff(j, c, lane));
                    ldsm2(bl, w1l + boff(j, c, lane));
                    const uint32_t* Ah = (c == 0) ? A0h : (c == 1) ? A1h : A2h;
                    const uint32_t* Al = (c == 0) ? A0l : (c == 1) ? A1l : A2l;
                    mma16816(C, Ah, bh);
                    mma16816(C, Al, bh);
                    mma16816(C, Ah, bl);
                }
                if (j < 4) {
                    zz[0][2*j] = sigm(C[0]); zz[0][2*j+1] = sigm(C[1]);
                    zz[1][2*j] = sigm(C[2]); zz[1][2*j+1] = sigm(C[3]);
                } else if (j < 8) {
                    int jj = j - 4;
                    gg[0][2*jj]   = h[u][0][2*jj]   * sigm(C[0]);
                    gg[0][2*jj+1] = h[u][0][2*jj+1] * sigm(C[1]);
                    gg[1][2*jj]   = h[u][1][2*jj]   * sigm(C[2]);
                    gg[1][2*jj+1] = h[u][1][2*jj+1] * sigm(C[3]);
                } else {
#pragma unroll
                    for (int e = 0; e < 4; e++) candC[j - 8][e] = C[e];
                }
            }

            // ---- gg -> A frags, MMA2 into candC ----
            uint32_t G0h[4], G0l[4], G1h[4], G1l[4];
#pragma unroll
            for (int i = 0; i < 2; i++) {
                float a0 = gg[i][0], a1 = gg[i][1], a2 = gg[i][2], a3 = gg[i][3];
                G0h[i]     = bf2(a0, a1); G0l[i]     = bf2(a0 - bfr(a0), a1 - bfr(a1));
                G0h[i + 2] = bf2(a2, a3); G0l[i + 2] = bf2(a2 - bfr(a2), a3 - bfr(a3));
                float c0 = gg[i][4], c1 = gg[i][5], c2 = gg[i][6], c3 = gg[i][7];
                G1h[i]     = bf2(c0, c1); G1l[i]     = bf2(c0 - bfr(c0), c1 - bfr(c1));
                G1h[i + 2] = bf2(c2, c3); G1l[i + 2] = bf2(c2 - bfr(c2), c3 - bfr(c3));
            }
#pragma unroll
            for (int j = 0; j < 4; j++) {
#pragma unroll
                for (int c = 0; c < 2; c++) {
                    uint32_t bh[2], bl[2];
                    ldsm2(bh, w2h + boff(j, c, lane));
                    ldsm2(bl, w2l + boff(j, c, lane));
                    const uint32_t* Gh = (c == 0) ? G0h : G1h;
                    const uint32_t* Gl = (c == 0) ? G0l : G1l;
                    mma16816(candC[j], Gh, bh);
                    mma16816(candC[j], Gl, bh);
                    mma16816(candC[j], Gh, bl);
                }
            }

            // ---- update + fused readout ----
            float p0 = 0.f, p1 = 0.f;
#pragma unroll
            for (int j = 0; j < 4; j++) {
                float t00 = tanha(candC[j][0]), t01 = tanha(candC[j][1]);
                float t10 = tanha(candC[j][2]), t11 = tanha(candC[j][3]);
                float hn;
                hn = t00 + zz[0][2*j]   * (h[u][0][2*j]   - t00); h[u][0][2*j]   = hn; p0 = fmaf(lrelu(hn), w1s[2*j],   p0);
                hn = t01 + zz[0][2*j+1] * (h[u][0][2*j+1] - t01); h[u][0][2*j+1] = hn; p0 = fmaf(lrelu(hn), w1s[2*j+1], p0);
                hn = t10 + zz[1][2*j]   * (h[u][1][2*j]   - t10); h[u][1][2*j]   = hn; p1 = fmaf(lrelu(hn), w1s[2*j],   p1);
                hn = t11 + zz[1][2*j+1] * (h[u][1][2*j+1] - t11); h[u][1][2*j+1] = hn; p1 = fmaf(lrelu(hn), w1s[2*j+1], p1);
            }
            p0 += __shfl_xor_sync(0xffffffffu, p0, 1);
            p0 += __shfl_xor_sync(0xffffffffu, p0, 2);
            p1 += __shfl_xor_sync(0xffffffffu, p1, 1);
            p1 += __shfl_xor_sync(0xffffffffu, p1, 2);
            float st = lrelu(p0 + b1s) * w2a[u] + lrelu(p1 + b1s) * w2b[u];
            st += __shfl_xor_sync(0xffffffffu, st, 4);
            st += __shfl_xor_sync(0xffffffffu, st, 8);
            st += __shfl_xor_sync(0xffffffffu, st, 16);
            if (lane == 0) g_scratch[t * NTILES_TOT + tiles[u]] = st;
        }
    }

    if (out_size >= N_NODES * 32) {
        const int hoff = out_size - N_NODES * 32;
#pragma unroll
        for (int u = 0; u < NT; u++)
#pragma unroll
            for (int j = 0; j < 4; j++) {
                *(float2*)(out + hoff + n0_[u] * 32 + 2 * (lane & 3) + 8 * j) =
                    make_float2(h[u][0][2*j], h[u][0][2*j+1]);
                *(float2*)(out + hoff + n1_[u] * 32 + 2 * (lane & 3) + 8 * j) =
                    make_float2(h[u][1][2*j], h[u][1][2*j+1]);
            }
    }
}

__global__ void __launch_bounds__(256, 1)
gru_mma(const float* __restrict__ x, const float* __restrict__ h0,
        const float* __restrict__ Wxz, const float* __restrict__ bxz,
        const float* __restrict__ Whz, const float* __restrict__ bhz,
        const float* __restrict__ Wxr, const float* __restrict__ bxr,
        const float* __restrict__ Whr, const float* __restrict__ bhr,
        const float* __restrict__ Wxh, const float* __restrict__ bxh,
        const float* __restrict__ Whh, const float* __restrict__ bhh,
        const float* __restrict__ W1,  const float* __restrict__ b1,
        const float* __restrict__ W2,
        float* __restrict__ out, int out_size)
{
    const int tid = threadIdx.x, b = blockIdx.x;
    // stage W1T[n=96][k=48->56] : k0-7 Wx*, k8 biases, k16-47 Wh{z,r}|0
    for (int i = tid; i < 96 * 56; i += 256) {
        int n = i / 56, k = i % 56;
        float v = 0.f;
        if (k < 8)       v = (n < 32) ? Wxz[k*32+n] : (n < 64) ? Wxr[k*32+n-32] : Wxh[k*32+n-64];
        else if (k == 8) v = (n < 32) ? bxz[n]+bhz[n] : (n < 64) ? bxr[n-32]+bhr[n-32] : bxh[n-64]+bhh[n-64];
        else if (k >= 16 && k < 48) {
            int kk = k - 16;
            v = (n < 32) ? Whz[kk*32+n] : (n < 64) ? Whr[kk*32+n-32] : 0.f;
        }
        __nv_bfloat16 hi = __float2bfloat16(v);
        sW1h[i] = hi;
        sW1l[i] = __float2bfloat16(v - __bfloat162float(hi));
    }
    // stage W2T[n=32][k=32->56] = Whh^T
    for (int i = tid; i < 32 * 56; i += 256) {
        int n = i / 56, k = i % 56;
        float v = (k < 32) ? Whh[k*32+n] : 0.f;
        __nv_bfloat16 hi = __float2bfloat16(v);
        sW2h[i] = hi;
        sW2l[i] = __float2bfloat16(v - __bfloat162float(hi));
    }
    __syncthreads();

    const int w = tid >> 5, lane = tid & 31;
    const int gw = b * 8 + w;
    const float b1s = b1[0];
    uint32_t w1h = s2u(sW1h), w1l = s2u(sW1l), w2h = s2u(sW2h), w2l = s2u(sW2l);

    if (b < NEXTRA && w == 0) {
        int tiles[2] = {gw, NWARPS + b};
        run_tiles<2>(tiles, x, h0, W1, b1s, W2, out, out_size, lane, w1h, w1l, w2h, w2l);
    } else {
        int tiles[1] = {gw};
        run_tiles<1>(tiles, x, h0, W1, b1s, W2, out, out_size, lane, w1h, w1l, w2h, w2l);
    }
}

__global__ void reduce_out(const float* __restrict__ b2,
                           float* __restrict__ out, int out_size)
{
    const int t = blockIdx.x;
    float s = 0.f;
    for (int w = threadIdx.x; w < NTILES_TOT; w += 256) s += g_scratch[t * NTILES_TOT + w];
#pragma unroll
    for (int o = 16; o; o >>= 1) s += __shfl_xor_sync(0xffffffffu, s, o);
    __shared__ float red[8];
    if ((threadIdx.x & 31) == 0) red[threadIdx.x >> 5] = s;
    __syncthreads();
    if (threadIdx.x < 8) {
        s = red[threadIdx.x];
#pragma unroll
        for (int o = 4; o; o >>= 1) s += __shfl_xor_sync(0x000000ffu, s, o);
        if (threadIdx.x == 0) {
            bool wr = (out_size >= T_STEPS + N_NODES * 32) || (out_size < N_NODES * 32);
            if (wr && t < out_size) out[t] = s + b2[0];
        }
    }
}

extern "C" void kernel_launch(void* const* d_in, const int* in_sizes, int n_in,
                              void* d_out, int out_size) {
    const float* x   = (const float*)d_in[0];
    const float* h0  = (const float*)d_in[3];
    const float* Wxz = (const float*)d_in[4];
    const float* bxz = (const float*)d_in[5];
    const float* Whz = (const float*)d_in[6];
    const float* bhz = (const float*)d_in[7];
    const float* Wxr = (const float*)d_in[8];
    const float* bxr = (const float*)d_in[9];
    const float* Whr = (const float*)d_in[10];
    const float* bhr = (const float*)d_in[11];
    const float* Wxh = (const float*)d_in[12];
    const float* bxh = (const float*)d_in[13];
    const float* Whh = (const float*)d_in[14];
    const float* bhh = (const float*)d_in[15];
    const float* W1  = (const float*)d_in[16];
    const float* b1  = (const float*)d_in[17];
    const float* W2  = (const float*)d_in[18];
    const float* b2  = (const float*)d_in[19];
    float* out = (float*)d_out;

    gru_mma<<<148, 256>>>(x, h0, Wxz, bxz, Whz, bhz, Wxr, bxr, Whr, bhr,
                          Wxh, bxh, Whh, bhh, W1, b1, W2, out, out_size);
    reduce_out<<<T_STEPS, 256>>>(b2, out, out_size);
}

// round 13
// speedup vs baseline: 3.6837x; 1.3075x over previous
#include <cuda_runtime.h>
#include <cuda_bf16.h>
#include <cstdint>

#define T_STEPS 64
#define N_NODES 20000
#define NTILES_TOT 1250     // 16 nodes per tile, 1 tile per active warp

__device__ float g_scratch[T_STEPS * NTILES_TOT];

__device__ __forceinline__ float tanha(float v) {
    float r; asm("tanh.approx.f32 %0, %1;" : "=f"(r) : "f"(v)); return r;
}
__device__ __forceinline__ float sigm(float v) { return fmaf(0.5f, tanha(0.5f * v), 0.5f); }
__device__ __forceinline__ float lrelu(float v) { return fmaxf(v, 0.01f * v); }
__device__ __forceinline__ float bfr(float v) { return __bfloat162float(__float2bfloat16(v)); }
__device__ __forceinline__ uint32_t bf2(float lo, float hi) {
    uint32_t r; asm("cvt.rn.bf16x2.f32 %0, %1, %2;" : "=r"(r) : "f"(hi), "f"(lo)); return r;
}
__device__ __forceinline__ uint32_t s2u(const void* p) {
    uint32_t a; asm("{ .reg .u64 t; cvta.to.shared.u64 t, %1; cvt.u32.u64 %0, t; }" : "=r"(a) : "l"(p));
    return a;
}
__device__ __forceinline__ void mma16816(float* c, const uint32_t* a, const uint32_t* b) {
    asm volatile("mma.sync.aligned.m16n8k16.row.col.f32.bf16.bf16.f32 "
        "{%0,%1,%2,%3}, {%4,%5,%6,%7}, {%8,%9}, {%0,%1,%2,%3};"
        : "+f"(c[0]), "+f"(c[1]), "+f"(c[2]), "+f"(c[3])
        : "r"(a[0]), "r"(a[1]), "r"(a[2]), "r"(a[3]), "r"(b[0]), "r"(b[1]));
}
__device__ __forceinline__ void ldsm2(uint32_t* d, uint32_t addr) {
    asm volatile("ldmatrix.sync.aligned.m8n8.x2.shared.b16 {%0,%1}, [%2];"
        : "=r"(d[0]), "=r"(d[1]) : "r"(addr));
}

// smem weight stores: rows [n][k], 56 halves (112B) stride
__shared__ __nv_bfloat16 sW1h[96 * 56], sW1l[96 * 56], sW2h[32 * 56], sW2l[32 * 56];

__device__ __forceinline__ uint32_t boff(int j, int c, int lane) {
    return (uint32_t)((8 * j + (lane & 7)) * 112 + c * 32 + ((lane >> 3) & 1) * 16);
}

__device__ void run_tile(int tile,
    const float* __restrict__ x, const float* __restrict__ h0,
    const float* __restrict__ W1, float b1s, const float* __restrict__ W2,
    float* __restrict__ out, int out_size, int lane,
    uint32_t w1h, uint32_t w1l, uint32_t w2h, uint32_t w2l)
{
    float w1s[8];
#pragma unroll
    for (int s = 0; s < 8; s++) w1s[s] = W1[2 * (lane & 3) + 8 * (s >> 1) + (s & 1)];

    const int n0 = tile * 16 + (lane >> 2);
    const int n1 = n0 + 8;
    float h[2][8];
#pragma unroll
    for (int s = 0; s < 8; s++) {
        int d = 2 * (lane & 3) + 8 * (s >> 1) + (s & 1);
        h[0][s] = h0[n0 * 32 + d];
        h[1][s] = h0[n1 * 32 + d];
    }
    const float w2a = W2[n0], w2b = W2[n1];
    const uint32_t biasreg = ((lane & 3) == 0) ? 0x00003F80u : 0u;  // bf16 1.0 at k==8

#pragma unroll 1
    for (int t = 0; t < T_STEPS; ++t) {
        // ---- A chunk0: x + bias ----
        const float* xb = x + (size_t)t * (N_NODES * 8);
        float2 xa = *(const float2*)(xb + (size_t)n0 * 8 + 2 * (lane & 3));
        float2 xc = *(const float2*)(xb + (size_t)n1 * 8 + 2 * (lane & 3));
        uint32_t A0h[4], A0l[4];
        A0h[0] = bf2(xa.x, xa.y); A0l[0] = bf2(xa.x - bfr(xa.x), xa.y - bfr(xa.y));
        A0h[1] = bf2(xc.x, xc.y); A0l[1] = bf2(xc.x - bfr(xc.x), xc.y - bfr(xc.y));
        A0h[2] = biasreg; A0h[3] = biasreg; A0l[2] = 0; A0l[3] = 0;
        // ---- A chunks 1,2 from h ----
        uint32_t A1h[4], A1l[4], A2h[4], A2l[4];
#pragma unroll
        for (int i = 0; i < 2; i++) {
            float a0 = h[i][0], a1 = h[i][1], a2 = h[i][2], a3 = h[i][3];
            A1h[i]     = bf2(a0, a1); A1l[i]     = bf2(a0 - bfr(a0), a1 - bfr(a1));
            A1h[i + 2] = bf2(a2, a3); A1l[i + 2] = bf2(a2 - bfr(a2), a3 - bfr(a3));
            float c0 = h[i][4], c1 = h[i][5], c2 = h[i][6], c3 = h[i][7];
            A2h[i]     = bf2(c0, c1); A2l[i]     = bf2(c0 - bfr(c0), c1 - bfr(c1));
            A2h[i + 2] = bf2(c2, c3); A2l[i + 2] = bf2(c2 - bfr(c2), c3 - bfr(c3));
        }

        // ---- MMA1: 12 n-tiles ----
        float zz[2][8], gg[2][8], candC[4][4];
#pragma unroll
        for (int j = 0; j < 12; j++) {
            float C[4] = {0.f, 0.f, 0.f, 0.f};
#pragma unroll
            for (int c = 0; c < 3; c++) {
                uint32_t bh[2], bl[2];
                ldsm2(bh, w1h + boff(j, c, lane));
                ldsm2(bl, w1l + boff(j, c, lane));
                const uint32_t* Ah = (c == 0) ? A0h : (c == 1) ? A1h : A2h;
                const uint32_t* Al = (c == 0) ? A0l : (c == 1) ? A1l : A2l;
                mma16816(C, Ah, bh);
                mma16816(C, Al, bh);
                mma16816(C, Ah, bl);
            }
            if (j < 4) {
                zz[0][2*j] = sigm(C[0]); zz[0][2*j+1] = sigm(C[1]);
                zz[1][2*j] = sigm(C[2]); zz[1][2*j+1] = sigm(C[3]);
            } else if (j < 8) {
                int jj = j - 4;
                gg[0][2*jj]   = h[0][2*jj]   * sigm(C[0]);
                gg[0][2*jj+1] = h[0][2*jj+1] * sigm(C[1]);
                gg[1][2*jj]   = h[1][2*jj]   * sigm(C[2]);
                gg[1][2*jj+1] = h[1][2*jj+1] * sigm(C[3]);
            } else {
#pragma unroll
                for (int e = 0; e < 4; e++) candC[j - 8][e] = C[e];
            }
        }

        // ---- gg -> A frags, MMA2 into candC ----
        uint32_t G0h[4], G0l[4], G1h[4], G1l[4];
#pragma unroll
        for (int i = 0; i < 2; i++) {
            float a0 = gg[i][0], a1 = gg[i][1], a2 = gg[i][2], a3 = gg[i][3];
            G0h[i]     = bf2(a0, a1); G0l[i]     = bf2(a0 - bfr(a0), a1 - bfr(a1));
            G0h[i + 2] = bf2(a2, a3); G0l[i + 2] = bf2(a2 - bfr(a2), a3 - bfr(a3));
            float c0 = gg[i][4], c1 = gg[i][5], c2 = gg[i][6], c3 = gg[i][7];
            G1h[i]     = bf2(c0, c1); G1l[i]     = bf2(c0 - bfr(c0), c1 - bfr(c1));
            G1h[i + 2] = bf2(c2, c3); G1l[i + 2] = bf2(c2 - bfr(c2), c3 - bfr(c3));
        }
#pragma unroll
        for (int j = 0; j < 4; j++) {
#pragma unroll
            for (int c = 0; c < 2; c++) {
                uint32_t bh[2], bl[2];
                ldsm2(bh, w2h + boff(j, c, lane));
                ldsm2(bl, w2l + boff(j, c, lane));
                const uint32_t* Gh = (c == 0) ? G0h : G1h;
                const uint32_t* Gl = (c == 0) ? G0l : G1l;
                mma16816(candC[j], Gh, bh);
                mma16816(candC[j], Gl, bh);
                mma16816(candC[j], Gh, bl);
            }
        }

        // ---- update + fused readout ----
        float p0 = 0.f, p1 = 0.f;
#pragma unroll
        for (int j = 0; j < 4; j++) {
            float t00 = tanha(candC[j][0]), t01 = tanha(candC[j][1]);
            float t10 = tanha(candC[j][2]), t11 = tanha(candC[j][3]);
            float hn;
            hn = t00 + zz[0][2*j]   * (h[0][2*j]   - t00); h[0][2*j]   = hn; p0 = fmaf(lrelu(hn), w1s[2*j],   p0);
            hn = t01 + zz[0][2*j+1] * (h[0][2*j+1] - t01); h[0][2*j+1] = hn; p0 = fmaf(lrelu(hn), w1s[2*j+1], p0);
            hn = t10 + zz[1][2*j]   * (h[1][2*j]   - t10); h[1][2*j]   = hn; p1 = fmaf(lrelu(hn), w1s[2*j],   p1);
            hn = t11 + zz[1][2*j+1] * (h[1][2*j+1] - t11); h[1][2*j+1] = hn; p1 = fmaf(lrelu(hn), w1s[2*j+1], p1);
        }
        p0 += __shfl_xor_sync(0xffffffffu, p0, 1);
        p0 += __shfl_xor_sync(0xffffffffu, p0, 2);
        p1 += __shfl_xor_sync(0xffffffffu, p1, 1);
        p1 += __shfl_xor_sync(0xffffffffu, p1, 2);
        float st = lrelu(p0 + b1s) * w2a + lrelu(p1 + b1s) * w2b;
        st += __shfl_xor_sync(0xffffffffu, st, 4);
        st += __shfl_xor_sync(0xffffffffu, st, 8);
        st += __shfl_xor_sync(0xffffffffu, st, 16);
        if (lane == 0) g_scratch[t * NTILES_TOT + tile] = st;
    }

    if (out_size >= N_NODES * 32) {
        const int hoff = out_size - N_NODES * 32;
#pragma unroll
        for (int j = 0; j < 4; j++) {
            *(float2*)(out + hoff + n0 * 32 + 2 * (lane & 3) + 8 * j) =
                make_float2(h[0][2*j], h[0][2*j+1]);
            *(float2*)(out + hoff + n1 * 32 + 2 * (lane & 3) + 8 * j) =
                make_float2(h[1][2*j], h[1][2*j+1]);
        }
    }
}

__global__ void __launch_bounds__(320, 1)
gru_mma(const float* __restrict__ x, const float* __restrict__ h0,
        const float* __restrict__ Wxz, const float* __restrict__ bxz,
        const float* __restrict__ Whz, const float* __restrict__ bhz,
        const float* __restrict__ Wxr, const float* __restrict__ bxr,
        const float* __restrict__ Whr, const float* __restrict__ bhr,
        const float* __restrict__ Wxh, const float* __restrict__ bxh,
        const float* __restrict__ Whh, const float* __restrict__ bhh,
        const float* __restrict__ W1,  const float* __restrict__ b1,
        const float* __restrict__ W2,
        float* __restrict__ out, int out_size)
{
    const int tid = threadIdx.x, b = blockIdx.x;
    // stage W1T[n=96][k=48->56] : k0-7 Wx*, k8 biases, k16-47 Wh{z,r}|0
    for (int i = tid; i < 96 * 56; i += 320) {
        int n = i / 56, k = i % 56;
        float v = 0.f;
        if (k < 8)       v = (n < 32) ? Wxz[k*32+n] : (n < 64) ? Wxr[k*32+n-32] : Wxh[k*32+n-64];
        else if (k == 8) v = (n < 32) ? bxz[n]+bhz[n] : (n < 64) ? bxr[n-32]+bhr[n-32] : bxh[n-64]+bhh[n-64];
        else if (k >= 16 && k < 48) {
            int kk = k - 16;
            v = (n < 32) ? Whz[kk*32+n] : (n < 64) ? Whr[kk*32+n-32] : 0.f;
        }
        __nv_bfloat16 hi = __float2bfloat16(v);
        sW1h[i] = hi;
        sW1l[i] = __float2bfloat16(v - __bfloat162float(hi));
    }
    // stage W2T[n=32][k=32->56] = Whh^T
    for (int i = tid; i < 32 * 56; i += 320) {
        int n = i / 56, k = i % 56;
        float v = (k < 32) ? Whh[k*32+n] : 0.f;
        __nv_bfloat16 hi = __float2bfloat16(v);
        sW2h[i] = hi;
        sW2l[i] = __float2bfloat16(v - __bfloat162float(hi));
    }
    __syncthreads();

    const int w = tid >> 5, lane = tid & 31;
    const float b1s = b1[0];
    uint32_t w1h = s2u(sW1h), w1l = s2u(sW1l), w2h = s2u(sW2h), w2l = s2u(sW2l);

    // blocks 0..65: 9 active warps; blocks 66..147: 8 active warps. Total 1250.
    const int nact = (b < 66) ? 9 : 8;
    if (w < nact) {
        const int tile = (b < 66) ? (9 * b + w) : (594 + 8 * (b - 66) + w);
        run_tile(tile, x, h0, W1, b1s, W2, out, out_size, lane, w1h, w1l, w2h, w2l);
    }
}

__global__ void reduce_out(const float* __restrict__ b2,
                           float* __restrict__ out, int out_size)
{
    const int t = blockIdx.x;
    float s = 0.f;
    for (int w = threadIdx.x; w < NTILES_TOT; w += 256) s += g_scratch[t * NTILES_TOT + w];
#pragma unroll
    for (int o = 16; o; o >>= 1) s += __shfl_xor_sync(0xffffffffu, s, o);
    __shared__ float red[8];
    if ((threadIdx.x & 31) == 0) red[threadIdx.x >> 5] = s;
    __syncthreads();
    if (threadIdx.x < 8) {
        s = red[threadIdx.x];
#pragma unroll
        for (int o = 4; o; o >>= 1) s += __shfl_xor_sync(0x000000ffu, s, o);
        if (threadIdx.x == 0) {
            bool wr = (out_size >= T_STEPS + N_NODES * 32) || (out_size < N_NODES * 32);
            if (wr && t < out_size) out[t] = s + b2[0];
        }
    }
}

extern "C" void kernel_launch(void* const* d_in, const int* in_sizes, int n_in,
                              void* d_out, int out_size) {
    const float* x   = (const float*)d_in[0];
    const float* h0  = (const float*)d_in[3];
    const float* Wxz = (const float*)d_in[4];
    const float* bxz = (const float*)d_in[5];
    const float* Whz = (const float*)d_in[6];
    const float* bhz = (const float*)d_in[7];
    const float* Wxr = (const float*)d_in[8];
    const float* bxr = (const float*)d_in[9];
    const float* Whr = (const float*)d_in[10];
    const float* bhr = (const float*)d_in[11];
    const float* Wxh = (const float*)d_in[12];
    const float* bxh = (const float*)d_in[13];
    const float* Whh = (const float*)d_in[14];
    const float* bhh = (const float*)d_in[15];
    const float* W1  = (const float*)d_in[16];
    const float* b1  = (const float*)d_in[17];
    const float* W2  = (const float*)d_in[18];
    const float* b2  = (const float*)d_in[19];
    float* out = (float*)d_out;

    gru_mma<<<148, 320>>>(x, h0, Wxz, bxz, Whz, bhz, Wxr, bxr, Whr, bhr,
                          Wxh, bxh, Whh, bhh, W1, b1, W2, out, out_size);
    reduce_out<<<T_STEPS, 256>>>(b2, out, out_size);
}

// round 14
// speedup vs baseline: 4.1088x; 1.1154x over previous
#include <cuda_runtime.h>
#include <cuda_bf16.h>
#include <cstdint>

#define T_STEPS 64
#define N_NODES 20000
#define NTILES_TOT 1250     // 16 nodes per tile, 1 tile per active warp

__device__ float g_scratch[T_STEPS * NTILES_TOT];

__device__ __forceinline__ float tanha(float v) {
    float r; asm("tanh.approx.f32 %0, %1;" : "=f"(r) : "f"(v)); return r;
}
__device__ __forceinline__ float sigm(float v) { return fmaf(0.5f, tanha(0.5f * v), 0.5f); }
__device__ __forceinline__ float lrelu(float v) { return fmaxf(v, 0.01f * v); }
__device__ __forceinline__ float bfr(float v) { return __bfloat162float(__float2bfloat16(v)); }
__device__ __forceinline__ uint32_t bf2(float lo, float hi) {
    uint32_t r; asm("cvt.rn.bf16x2.f32 %0, %1, %2;" : "=r"(r) : "f"(hi), "f"(lo)); return r;
}
__device__ __forceinline__ uint32_t s2u(const void* p) {
    uint32_t a; asm("{ .reg .u64 t; cvta.to.shared.u64 t, %1; cvt.u32.u64 %0, t; }" : "=r"(a) : "l"(p));
    return a;
}
__device__ __forceinline__ void mma16816(float* c, const uint32_t* a, const uint32_t* b) {
    asm volatile("mma.sync.aligned.m16n8k16.row.col.f32.bf16.bf16.f32 "
        "{%0,%1,%2,%3}, {%4,%5,%6,%7}, {%8,%9}, {%0,%1,%2,%3};"
        : "+f"(c[0]), "+f"(c[1]), "+f"(c[2]), "+f"(c[3])
        : "r"(a[0]), "r"(a[1]), "r"(a[2]), "r"(a[3]), "r"(b[0]), "r"(b[1]));
}
__device__ __forceinline__ void ldsm2(uint32_t* d, uint32_t addr) {
    asm volatile("ldmatrix.sync.aligned.m8n8.x2.shared.b16 {%0,%1}, [%2];"
        : "=r"(d[0]), "=r"(d[1]) : "r"(addr));
}

// smem weight stores: rows [n][k], 56 halves (112B) stride
__shared__ __nv_bfloat16 sW1h[96 * 56], sW1l[96 * 56], sW2h[32 * 56], sW2l[32 * 56];

__device__ __forceinline__ uint32_t boff(int j, int c, int lane) {
    return (uint32_t)((8 * j + (lane & 7)) * 112 + c * 32 + ((lane >> 3) & 1) * 16);
}

__device__ void run_tile(int tile,
    const float* __restrict__ x, const float* __restrict__ h0,
    const float* __restrict__ W1, float b1s, const float* __restrict__ W2,
    float* __restrict__ out, int out_size, int lane,
    uint32_t w1h, uint32_t w1l, uint32_t w2h, uint32_t w2l)
{
    float w1s[8];
#pragma unroll
    for (int s = 0; s < 8; s++) w1s[s] = W1[2 * (lane & 3) + 8 * (s >> 1) + (s & 1)];

    const int n0 = tile * 16 + (lane >> 2);
    const int n1 = n0 + 8;
    float h[2][8];
#pragma unroll
    for (int s = 0; s < 8; s++) {
        int d = 2 * (lane & 3) + 8 * (s >> 1) + (s & 1);
        h[0][s] = h0[n0 * 32 + d];
        h[1][s] = h0[n1 * 32 + d];
    }
    const float w2a = W2[n0], w2b = W2[n1];
    const uint32_t biasreg = ((lane & 3) == 0) ? 0x00003F80u : 0u;  // bf16 1.0 at k==8

#pragma unroll 1
    for (int t = 0; t < T_STEPS; ++t) {
        // ---- A chunk0: x + bias ----
        const float* xb = x + (size_t)t * (N_NODES * 8);
        float2 xa = *(const float2*)(xb + (size_t)n0 * 8 + 2 * (lane & 3));
        float2 xc = *(const float2*)(xb + (size_t)n1 * 8 + 2 * (lane & 3));
        uint32_t A0h[4], A0l[4];
        A0h[0] = bf2(xa.x, xa.y); A0l[0] = bf2(xa.x - bfr(xa.x), xa.y - bfr(xa.y));
        A0h[1] = bf2(xc.x, xc.y); A0l[1] = bf2(xc.x - bfr(xc.x), xc.y - bfr(xc.y));
        A0h[2] = biasreg; A0h[3] = biasreg; A0l[2] = 0; A0l[3] = 0;
        // ---- A chunks 1,2 from h ----
        uint32_t A1h[4], A1l[4], A2h[4], A2l[4];
#pragma unroll
        for (int i = 0; i < 2; i++) {
            float a0 = h[i][0], a1 = h[i][1], a2 = h[i][2], a3 = h[i][3];
            A1h[i]     = bf2(a0, a1); A1l[i]     = bf2(a0 - bfr(a0), a1 - bfr(a1));
            A1h[i + 2] = bf2(a2, a3); A1l[i + 2] = bf2(a2 - bfr(a2), a3 - bfr(a3));
            float c0 = h[i][4], c1 = h[i][5], c2 = h[i][6], c3 = h[i][7];
            A2h[i]     = bf2(c0, c1); A2l[i]     = bf2(c0 - bfr(c0), c1 - bfr(c1));
            A2h[i + 2] = bf2(c2, c3); A2l[i + 2] = bf2(c2 - bfr(c2), c3 - bfr(c3));
        }

        // ---- MMA1: z,r (j<8, full K) + cand x-part (j>=8, chunk 0 ONLY —
        //      B1 cand columns are zero for k>=16, skip the dead MMAs) ----
        float zz[2][8], gg[2][8], candC[4][4];
#pragma unroll
        for (int j = 0; j < 12; j++) {
            float C[4] = {0.f, 0.f, 0.f, 0.f};
            const int nch = (j < 8) ? 3 : 1;
#pragma unroll
            for (int c = 0; c < 3; c++) {
                if (c >= nch) break;
                uint32_t bh[2], bl[2];
                ldsm2(bh, w1h + boff(j, c, lane));
                ldsm2(bl, w1l + boff(j, c, lane));
                const uint32_t* Ah = (c == 0) ? A0h : (c == 1) ? A1h : A2h;
                const uint32_t* Al = (c == 0) ? A0l : (c == 1) ? A1l : A2l;
                mma16816(C, Ah, bh);
                mma16816(C, Al, bh);
                mma16816(C, Ah, bl);
            }
            if (j < 4) {
                zz[0][2*j] = sigm(C[0]); zz[0][2*j+1] = sigm(C[1]);
                zz[1][2*j] = sigm(C[2]); zz[1][2*j+1] = sigm(C[3]);
            } else if (j < 8) {
                int jj = j - 4;
                gg[0][2*jj]   = h[0][2*jj]   * sigm(C[0]);
                gg[0][2*jj+1] = h[0][2*jj+1] * sigm(C[1]);
                gg[1][2*jj]   = h[1][2*jj]   * sigm(C[2]);
                gg[1][2*jj+1] = h[1][2*jj+1] * sigm(C[3]);
            } else {
#pragma unroll
                for (int e = 0; e < 4; e++) candC[j - 8][e] = C[e];
            }
        }

        // ---- gg -> A frags, MMA2 into candC ----
        uint32_t G0h[4], G0l[4], G1h[4], G1l[4];
#pragma unroll
        for (int i = 0; i < 2; i++) {
            float a0 = gg[i][0], a1 = gg[i][1], a2 = gg[i][2], a3 = gg[i][3];
            G0h[i]     = bf2(a0, a1); G0l[i]     = bf2(a0 - bfr(a0), a1 - bfr(a1));
            G0h[i + 2] = bf2(a2, a3); G0l[i + 2] = bf2(a2 - bfr(a2), a3 - bfr(a3));
            float c0 = gg[i][4], c1 = gg[i][5], c2 = gg[i][6], c3 = gg[i][7];
            G1h[i]     = bf2(c0, c1); G1l[i]     = bf2(c0 - bfr(c0), c1 - bfr(c1));
            G1h[i + 2] = bf2(c2, c3); G1l[i + 2] = bf2(c2 - bfr(c2), c3 - bfr(c3));
        }
#pragma unroll
        for (int j = 0; j < 4; j++) {
#pragma unroll
            for (int c = 0; c < 2; c++) {
                uint32_t bh[2], bl[2];
                ldsm2(bh, w2h + boff(j, c, lane));
                ldsm2(bl, w2l + boff(j, c, lane));
                const uint32_t* Gh = (c == 0) ? G0h : G1h;
                const uint32_t* Gl = (c == 0) ? G0l : G1l;
                mma16816(candC[j], Gh, bh);
                mma16816(candC[j], Gl, bh);
                mma16816(candC[j], Gh, bl);
            }
        }

        // ---- update + fused readout ----
        float p0 = 0.f, p1 = 0.f;
#pragma unroll
        for (int j = 0; j < 4; j++) {
            float t00 = tanha(candC[j][0]), t01 = tanha(candC[j][1]);
            float t10 = tanha(candC[j][2]), t11 = tanha(candC[j][3]);
            float hn;
            hn = t00 + zz[0][2*j]   * (h[0][2*j]   - t00); h[0][2*j]   = hn; p0 = fmaf(lrelu(hn), w1s[2*j],   p0);
            hn = t01 + zz[0][2*j+1] * (h[0][2*j+1] - t01); h[0][2*j+1] = hn; p0 = fmaf(lrelu(hn), w1s[2*j+1], p0);
            hn = t10 + zz[1][2*j]   * (h[1][2*j]   - t10); h[1][2*j]   = hn; p1 = fmaf(lrelu(hn), w1s[2*j],   p1);
            hn = t11 + zz[1][2*j+1] * (h[1][2*j+1] - t11); h[1][2*j+1] = hn; p1 = fmaf(lrelu(hn), w1s[2*j+1], p1);
        }
        p0 += __shfl_xor_sync(0xffffffffu, p0, 1);
        p0 += __shfl_xor_sync(0xffffffffu, p0, 2);
        p1 += __shfl_xor_sync(0xffffffffu, p1, 1);
        p1 += __shfl_xor_sync(0xffffffffu, p1, 2);
        float st = lrelu(p0 + b1s) * w2a + lrelu(p1 + b1s) * w2b;
        st += __shfl_xor_sync(0xffffffffu, st, 4);
        st += __shfl_xor_sync(0xffffffffu, st, 8);
        st += __shfl_xor_sync(0xffffffffu, st, 16);
        if (lane == 0) g_scratch[t * NTILES_TOT + tile] = st;
    }

    if (out_size >= N_NODES * 32) {
        const int hoff = out_size - N_NODES * 32;
#pragma unroll
        for (int j = 0; j < 4; j++) {
            *(float2*)(out + hoff + n0 * 32 + 2 * (lane & 3) + 8 * j) =
                make_float2(h[0][2*j], h[0][2*j+1]);
            *(float2*)(out + hoff + n1 * 32 + 2 * (lane & 3) + 8 * j) =
                make_float2(h[1][2*j], h[1][2*j+1]);
        }
    }
}

__global__ void __launch_bounds__(320, 1)
gru_mma(const float* __restrict__ x, const float* __restrict__ h0,
        const float* __restrict__ Wxz, const float* __restrict__ bxz,
        const float* __restrict__ Whz, const float* __restrict__ bhz,
        const float* __restrict__ Wxr, const float* __restrict__ bxr,
        const float* __restrict__ Whr, const float* __restrict__ bhr,
        const float* __restrict__ Wxh, const float* __restrict__ bxh,
        const float* __restrict__ Whh, const float* __restrict__ bhh,
        const float* __restrict__ W1,  const float* __restrict__ b1,
        const float* __restrict__ W2,
        float* __restrict__ out, int out_size)
{
    const int tid = threadIdx.x, b = blockIdx.x;
    // stage W1T[n=96][k=48->56] : k0-7 Wx*, k8 biases, k16-47 Wh{z,r}|0
    for (int i = tid; i < 96 * 56; i += 320) {
        int n = i / 56, k = i % 56;
        float v = 0.f;
        if (k < 8)       v = (n < 32) ? Wxz[k*32+n] : (n < 64) ? Wxr[k*32+n-32] : Wxh[k*32+n-64];
        else if (k == 8) v = (n < 32) ? bxz[n]+bhz[n] : (n < 64) ? bxr[n-32]+bhr[n-32] : bxh[n-64]+bhh[n-64];
        else if (k >= 16 && k < 48) {
            int kk = k - 16;
            v = (n < 32) ? Whz[kk*32+n] : (n < 64) ? Whr[kk*32+n-32] : 0.f;
        }
        __nv_bfloat16 hi = __float2bfloat16(v);
        sW1h[i] = hi;
        sW1l[i] = __float2bfloat16(v - __bfloat162float(hi));
    }
    // stage W2T[n=32][k=32->56] = Whh^T
    for (int i = tid; i < 32 * 56; i += 320) {
        int n = i / 56, k = i % 56;
        float v = (k < 32) ? Whh[k*32+n] : 0.f;
        __nv_bfloat16 hi = __float2bfloat16(v);
        sW2h[i] = hi;
        sW2l[i] = __float2bfloat16(v - __bfloat162float(hi));
    }
    __syncthreads();

    const int w = tid >> 5, lane = tid & 31;
    const float b1s = b1[0];
    uint32_t w1h = s2u(sW1h), w1l = s2u(sW1l), w2h = s2u(sW2h), w2l = s2u(sW2l);

    // blocks 0..65: 9 active warps; blocks 66..147: 8 active warps. Total 1250.
    const int nact = (b < 66) ? 9 : 8;
    if (w < nact) {
        const int tile = (b < 66) ? (9 * b + w) : (594 + 8 * (b - 66) + w);
        run_tile(tile, x, h0, W1, b1s, W2, out, out_size, lane, w1h, w1l, w2h, w2l);
    }
}

__global__ void reduce_out(const float* __restrict__ b2,
                           float* __restrict__ out, int out_size)
{
    const int t = blockIdx.x;
    float s = 0.f;
    for (int w = threadIdx.x; w < NTILES_TOT; w += 256) s += g_scratch[t * NTILES_TOT + w];
#pragma unroll
    for (int o = 16; o; o >>= 1) s += __shfl_xor_sync(0xffffffffu, s, o);
    __shared__ float red[8];
    if ((threadIdx.x & 31) == 0) red[threadIdx.x >> 5] = s;
    __syncthreads();
    if (threadIdx.x < 8) {
        s = red[threadIdx.x];
#pragma unroll
        for (int o = 4; o; o >>= 1) s += __shfl_xor_sync(0x000000ffu, s, o);
        if (threadIdx.x == 0) {
            bool wr = (out_size >= T_STEPS + N_NODES * 32) || (out_size < N_NODES * 32);
            if (wr && t < out_size) out[t] = s + b2[0];
        }
    }
}

extern "C" void kernel_launch(void* const* d_in, const int* in_sizes, int n_in,
                              void* d_out, int out_size) {
    const float* x   = (const float*)d_in[0];
    const float* h0  = (const float*)d_in[3];
    const float* Wxz = (const float*)d_in[4];
    const float* bxz = (const float*)d_in[5];
    const float* Whz = (const float*)d_in[6];
    const float* bhz = (const float*)d_in[7];
    const float* Wxr = (const float*)d_in[8];
    const float* bxr = (const float*)d_in[9];
    const float* Whr = (const float*)d_in[10];
    const float* bhr = (const float*)d_in[11];
    const float* Wxh = (const float*)d_in[12];
    const float* bxh = (const float*)d_in[13];
    const float* Whh = (const float*)d_in[14];
    const float* bhh = (const float*)d_in[15];
    const float* W1  = (const float*)d_in[16];
    const float* b1  = (const float*)d_in[17];
    const float* W2  = (const float*)d_in[18];
    const float* b2  = (const float*)d_in[19];
    float* out = (float*)d_out;

    gru_mma<<<148, 320>>>(x, h0, Wxz, bxz, Whz, bhz, Wxr, bxr, Whr, bhr,
                          Wxh, bxh, Whh, bhh, W1, b1, W2, out, out_size);
    reduce_out<<<T_STEPS, 256>>>(b2, out, out_size);
}

// round 15
// speedup vs baseline: 4.3465x; 1.0579x over previous
#include <cuda_runtime.h>
#include <cuda_bf16.h>
#include <cstdint>

#define T_STEPS 64
#define N_NODES 20000
#define NTILES_TOT 1250     // 16 nodes per tile, 1 tile per active warp

__device__ float g_scratch[T_STEPS * NTILES_TOT];

__device__ __forceinline__ float tanha(float v) {
    float r; asm("tanh.approx.f32 %0, %1;" : "=f"(r) : "f"(v)); return r;
}
__device__ __forceinline__ float sigm(float v) { return fmaf(0.5f, tanha(0.5f * v), 0.5f); }
__device__ __forceinline__ float lrelu(float v) { return fmaxf(v, 0.01f * v); }
__device__ __forceinline__ float bfr(float v) { return __bfloat162float(__float2bfloat16(v)); }
__device__ __forceinline__ uint32_t bf2(float lo, float hi) {
    uint32_t r; asm("cvt.rn.bf16x2.f32 %0, %1, %2;" : "=r"(r) : "f"(hi), "f"(lo)); return r;
}
__device__ __forceinline__ uint32_t s2u(const void* p) {
    uint32_t a; asm("{ .reg .u64 t; cvta.to.shared.u64 t, %1; cvt.u32.u64 %0, t; }" : "=r"(a) : "l"(p));
    return a;
}
__device__ __forceinline__ void mma16816(float* c, const uint32_t* a, const uint32_t* b) {
    asm volatile("mma.sync.aligned.m16n8k16.row.col.f32.bf16.bf16.f32 "
        "{%0,%1,%2,%3}, {%4,%5,%6,%7}, {%8,%9}, {%0,%1,%2,%3};"
        : "+f"(c[0]), "+f"(c[1]), "+f"(c[2]), "+f"(c[3])
        : "r"(a[0]), "r"(a[1]), "r"(a[2]), "r"(a[3]), "r"(b[0]), "r"(b[1]));
}
__device__ __forceinline__ void mma16808(float* c, const uint32_t* a, uint32_t b) {
    asm volatile("mma.sync.aligned.m16n8k8.row.col.f32.bf16.bf16.f32 "
        "{%0,%1,%2,%3}, {%4,%5}, {%6}, {%0,%1,%2,%3};"
        : "+f"(c[0]), "+f"(c[1]), "+f"(c[2]), "+f"(c[3])
        : "r"(a[0]), "r"(a[1]), "r"(b));
}
__device__ __forceinline__ void ldsm2(uint32_t* d, uint32_t addr) {
    asm volatile("ldmatrix.sync.aligned.m8n8.x2.shared.b16 {%0,%1}, [%2];"
        : "=r"(d[0]), "=r"(d[1]) : "r"(addr));
}
__device__ __forceinline__ uint32_t ldsm1(uint32_t addr) {
    uint32_t d;
    asm volatile("ldmatrix.sync.aligned.m8n8.x1.shared.b16 {%0}, [%1];"
        : "=r"(d) : "r"(addr));
    return d;
}

// smem weight stores: rows [n][k], 56 halves (112B) stride
__shared__ __nv_bfloat16 sW1h[96 * 56], sW1l[96 * 56], sW2h[32 * 56], sW2l[32 * 56];

__device__ __forceinline__ uint32_t boff(int j, int c, int lane) {
    return (uint32_t)((8 * j + (lane & 7)) * 112 + c * 32 + ((lane >> 3) & 1) * 16);
}

__device__ void run_tile(int tile,
    const float* __restrict__ x, const float* __restrict__ h0,
    const float* __restrict__ W1, float b1s, const float* __restrict__ W2,
    const float* __restrict__ bxz, const float* __restrict__ bhz,
    const float* __restrict__ bxr, const float* __restrict__ bhr,
    const float* __restrict__ bxh, const float* __restrict__ bhh,
    float* __restrict__ out, int out_size, int lane,
    uint32_t w1h, uint32_t w1l, uint32_t w2h, uint32_t w2l)
{
    float w1s[8];
#pragma unroll
    for (int s = 0; s < 8; s++) w1s[s] = W1[2 * (lane & 3) + 8 * (s >> 1) + (s & 1)];

    // per-thread C-init biases: j-tile j covers cols n = 8*jj + 2*(lane&3)+{0,1}
    float bC[12][2];
#pragma unroll
    for (int jj = 0; jj < 4; jj++) {
#pragma unroll
        for (int e = 0; e < 2; e++) {
            int n = 8 * jj + 2 * (lane & 3) + e;
            bC[jj][e]     = bxz[n] + bhz[n];
            bC[jj + 4][e] = bxr[n] + bhr[n];
            bC[jj + 8][e] = bxh[n] + bhh[n];
        }
    }

    const int n0 = tile * 16 + (lane >> 2);
    const int n1 = n0 + 8;
    float h[2][8];
#pragma unroll
    for (int s = 0; s < 8; s++) {
        int d = 2 * (lane & 3) + 8 * (s >> 1) + (s & 1);
        h[0][s] = h0[n0 * 32 + d];
        h[1][s] = h0[n1 * 32 + d];
    }
    const float w2a = W2[n0], w2b = W2[n1];

#pragma unroll 1
    for (int t = 0; t < T_STEPS; ++t) {
        // ---- A chunk0 (K=8): x only ----
        const float* xb = x + (size_t)t * (N_NODES * 8);
        float2 xa = *(const float2*)(xb + (size_t)n0 * 8 + 2 * (lane & 3));
        float2 xc = *(const float2*)(xb + (size_t)n1 * 8 + 2 * (lane & 3));
        uint32_t A0h[2], A0l[2];
        A0h[0] = bf2(xa.x, xa.y); A0l[0] = bf2(xa.x - bfr(xa.x), xa.y - bfr(xa.y));
        A0h[1] = bf2(xc.x, xc.y); A0l[1] = bf2(xc.x - bfr(xc.x), xc.y - bfr(xc.y));
        // ---- A chunks 1,2 from h ----
        uint32_t A1h[4], A1l[4], A2h[4], A2l[4];
#pragma unroll
        for (int i = 0; i < 2; i++) {
            float a0 = h[i][0], a1 = h[i][1], a2 = h[i][2], a3 = h[i][3];
            A1h[i]     = bf2(a0, a1); A1l[i]     = bf2(a0 - bfr(a0), a1 - bfr(a1));
            A1h[i + 2] = bf2(a2, a3); A1l[i + 2] = bf2(a2 - bfr(a2), a3 - bfr(a3));
            float c0 = h[i][4], c1 = h[i][5], c2 = h[i][6], c3 = h[i][7];
            A2h[i]     = bf2(c0, c1); A2l[i]     = bf2(c0 - bfr(c0), c1 - bfr(c1));
            A2h[i + 2] = bf2(c2, c3); A2l[i + 2] = bf2(c2 - bfr(c2), c3 - bfr(c3));
        }

        // ---- MMA1: bias in C-init; x via k8 MMA; h via k16 (j<8 only) ----
        float zz[2][8], gg[2][8], candC[4][4];
#pragma unroll
        for (int j = 0; j < 12; j++) {
            float C[4] = {bC[j][0], bC[j][1], bC[j][0], bC[j][1]};
            // x-part, K=8, 3 split terms
            {
                uint32_t bh = ldsm1(w1h + boff(j, 0, lane));
                uint32_t bl = ldsm1(w1l + boff(j, 0, lane));
                mma16808(C, A0h, bh);
                mma16808(C, A0l, bh);
                mma16808(C, A0h, bl);
            }
            if (j < 8) {
#pragma unroll
                for (int c = 1; c < 3; c++) {
                    uint32_t bh[2], bl[2];
                    ldsm2(bh, w1h + boff(j, c, lane));
                    ldsm2(bl, w1l + boff(j, c, lane));
                    const uint32_t* Ah = (c == 1) ? A1h : A2h;
                    const uint32_t* Al = (c == 1) ? A1l : A2l;
                    mma16816(C, Ah, bh);
                    mma16816(C, Al, bh);
                    mma16816(C, Ah, bl);
                }
            }
            if (j < 4) {
                zz[0][2*j] = sigm(C[0]); zz[0][2*j+1] = sigm(C[1]);
                zz[1][2*j] = sigm(C[2]); zz[1][2*j+1] = sigm(C[3]);
            } else if (j < 8) {
                int jj = j - 4;
                gg[0][2*jj]   = h[0][2*jj]   * sigm(C[0]);
                gg[0][2*jj+1] = h[0][2*jj+1] * sigm(C[1]);
                gg[1][2*jj]   = h[1][2*jj]   * sigm(C[2]);
                gg[1][2*jj+1] = h[1][2*jj+1] * sigm(C[3]);
            } else {
#pragma unroll
                for (int e = 0; e < 4; e++) candC[j - 8][e] = C[e];
            }
        }

        // ---- gg -> A frags, MMA2 into candC ----
        uint32_t G0h[4], G0l[4], G1h[4], G1l[4];
#pragma unroll
        for (int i = 0; i < 2; i++) {
            float a0 = gg[i][0], a1 = gg[i][1], a2 = gg[i][2], a3 = gg[i][3];
            G0h[i]     = bf2(a0, a1); G0l[i]     = bf2(a0 - bfr(a0), a1 - bfr(a1));
            G0h[i + 2] = bf2(a2, a3); G0l[i + 2] = bf2(a2 - bfr(a2), a3 - bfr(a3));
            float c0 = gg[i][4], c1 = gg[i][5], c2 = gg[i][6], c3 = gg[i][7];
            G1h[i]     = bf2(c0, c1); G1l[i]     = bf2(c0 - bfr(c0), c1 - bfr(c1));
            G1h[i + 2] = bf2(c2, c3); G1l[i + 2] = bf2(c2 - bfr(c2), c3 - bfr(c3));
        }
#pragma unroll
        for (int j = 0; j < 4; j++) {
#pragma unroll
            for (int c = 0; c < 2; c++) {
                uint32_t bh[2], bl[2];
                ldsm2(bh, w2h + boff(j, c, lane));
                ldsm2(bl, w2l + boff(j, c, lane));
                const uint32_t* Gh = (c == 0) ? G0h : G1h;
                const uint32_t* Gl = (c == 0) ? G0l : G1l;
                mma16816(candC[j], Gh, bh);
                mma16816(candC[j], Gl, bh);
                mma16816(candC[j], Gh, bl);
            }
        }

        // ---- update + fused readout ----
        float p0 = 0.f, p1 = 0.f;
#pragma unroll
        for (int j = 0; j < 4; j++) {
            float t00 = tanha(candC[j][0]), t01 = tanha(candC[j][1]);
            float t10 = tanha(candC[j][2]), t11 = tanha(candC[j][3]);
            float hn;
            hn = t00 + zz[0][2*j]   * (h[0][2*j]   - t00); h[0][2*j]   = hn; p0 = fmaf(lrelu(hn), w1s[2*j],   p0);
            hn = t01 + zz[0][2*j+1] * (h[0][2*j+1] - t01); h[0][2*j+1] = hn; p0 = fmaf(lrelu(hn), w1s[2*j+1], p0);
            hn = t10 + zz[1][2*j]   * (h[1][2*j]   - t10); h[1][2*j]   = hn; p1 = fmaf(lrelu(hn), w1s[2*j],   p1);
            hn = t11 + zz[1][2*j+1] * (h[1][2*j+1] - t11); h[1][2*j+1] = hn; p1 = fmaf(lrelu(hn), w1s[2*j+1], p1);
        }
        p0 += __shfl_xor_sync(0xffffffffu, p0, 1);
        p0 += __shfl_xor_sync(0xffffffffu, p0, 2);
        p1 += __shfl_xor_sync(0xffffffffu, p1, 1);
        p1 += __shfl_xor_sync(0xffffffffu, p1, 2);
        float st = lrelu(p0 + b1s) * w2a + lrelu(p1 + b1s) * w2b;
        st += __shfl_xor_sync(0xffffffffu, st, 4);
        st += __shfl_xor_sync(0xffffffffu, st, 8);
        st += __shfl_xor_sync(0xffffffffu, st, 16);
        if (lane == 0) g_scratch[t * NTILES_TOT + tile] = st;
    }

    if (out_size >= N_NODES * 32) {
        const int hoff = out_size - N_NODES * 32;
#pragma unroll
        for (int j = 0; j < 4; j++) {
            *(float2*)(out + hoff + n0 * 32 + 2 * (lane & 3) + 8 * j) =
                make_float2(h[0][2*j], h[0][2*j+1]);
            *(float2*)(out + hoff + n1 * 32 + 2 * (lane & 3) + 8 * j) =
                make_float2(h[1][2*j], h[1][2*j+1]);
        }
    }
}

__global__ void __launch_bounds__(320, 1)
gru_mma(const float* __restrict__ x, const float* __restrict__ h0,
        const float* __restrict__ Wxz, const float* __restrict__ bxz,
        const float* __restrict__ Whz, const float* __restrict__ bhz,
        const float* __restrict__ Wxr, const float* __restrict__ bxr,
        const float* __restrict__ Whr, const float* __restrict__ bhr,
        const float* __restrict__ Wxh, const float* __restrict__ bxh,
        const float* __restrict__ Whh, const float* __restrict__ bhh,
        const float* __restrict__ W1,  const float* __restrict__ b1,
        const float* __restrict__ W2,
        float* __restrict__ out, int out_size)
{
    const int tid = threadIdx.x, b = blockIdx.x;
    // stage W1T[n=96][k=48->56] : k0-7 Wx*, k16-47 Wh{z,r}|0 (biases now in C-init)
    for (int i = tid; i < 96 * 56; i += 320) {
        int n = i / 56, k = i % 56;
        float v = 0.f;
        if (k < 8) v = (n < 32) ? Wxz[k*32+n] : (n < 64) ? Wxr[k*32+n-32] : Wxh[k*32+n-64];
        else if (k >= 16 && k < 48) {
            int kk = k - 16;
            v = (n < 32) ? Whz[kk*32+n] : (n < 64) ? Whr[kk*32+n-32] : 0.f;
        }
        __nv_bfloat16 hi = __float2bfloat16(v);
        sW1h[i] = hi;
        sW1l[i] = __float2bfloat16(v - __bfloat162float(hi));
    }
    // stage W2T[n=32][k=32->56] = Whh^T
    for (int i = tid; i < 32 * 56; i += 320) {
        int n = i / 56, k = i % 56;
        float v = (k < 32) ? Whh[k*32+n] : 0.f;
        __nv_bfloat16 hi = __float2bfloat16(v);
        sW2h[i] = hi;
        sW2l[i] = __float2bfloat16(v - __bfloat162float(hi));
    }
    __syncthreads();

    const int w = tid >> 5, lane = tid & 31;
    const float b1s = b1[0];
    uint32_t w1h = s2u(sW1h), w1l = s2u(sW1l), w2h = s2u(sW2h), w2l = s2u(sW2l);

    // blocks 0..65: 9 active warps; blocks 66..147: 8 active warps. Total 1250.
    const int nact = (b < 66) ? 9 : 8;
    if (w < nact) {
        const int tile = (b < 66) ? (9 * b + w) : (594 + 8 * (b - 66) + w);
        run_tile(tile, x, h0, W1, b1s, W2, bxz, bhz, bxr, bhr, bxh, bhh,
                 out, out_size, lane, w1h, w1l, w2h, w2l);
    }
}

__global__ void reduce_out(const float* __restrict__ b2,
                           float* __restrict__ out, int out_size)
{
    const int t = blockIdx.x;
    float s = 0.f;
    for (int w = threadIdx.x; w < NTILES_TOT; w += 256) s += g_scratch[t * NTILES_TOT + w];
#pragma unroll
    for (int o = 16; o; o >>= 1) s += __shfl_xor_sync(0xffffffffu, s, o);
    __shared__ float red[8];
    if ((threadIdx.x & 31) == 0) red[threadIdx.x >> 5] = s;
    __syncthreads();
    if (threadIdx.x < 8) {
        s = red[threadIdx.x];
#pragma unroll
        for (int o = 4; o; o >>= 1) s += __shfl_xor_sync(0x000000ffu, s, o);
        if (threadIdx.x == 0) {
            bool wr = (out_size >= T_STEPS + N_NODES * 32) || (out_size < N_NODES * 32);
            if (wr && t < out_size) out[t] = s + b2[0];
        }
    }
}

extern "C" void kernel_launch(void* const* d_in, const int* in_sizes, int n_in,
                              void* d_out, int out_size) {
    const float* x   = (const float*)d_in[0];
    const float* h0  = (const float*)d_in[3];
    const float* Wxz = (const float*)d_in[4];
    const float* bxz = (const float*)d_in[5];
    const float* Whz = (const float*)d_in[6];
    const float* bhz = (const float*)d_in[7];
    const float* Wxr = (const float*)d_in[8];
    const float* bxr = (const float*)d_in[9];
    const float* Whr = (const float*)d_in[10];
    const float* bhr = (const float*)d_in[11];
    const float* Wxh = (const float*)d_in[12];
    const float* bxh = (const float*)d_in[13];
    const float* Whh = (const float*)d_in[14];
    const float* bhh = (const float*)d_in[15];
    const float* W1  = (const float*)d_in[16];
    const float* b1  = (const float*)d_in[17];
    const float* W2  = (const float*)d_in[18];
    const float* b2  = (const float*)d_in[19];
    float* out = (float*)d_out;

    gru_mma<<<148, 320>>>(x, h0, Wxz, bxz, Whz, bhz, Wxr, bxr, Whr, bhr,
                          Wxh, bxh, Whh, bhh, W1, b1, W2, out, out_size);
    reduce_out<<<T_STEPS, 256>>>(b2, out, out_size);
}

// round 16
// speedup vs baseline: 5.1381x; 1.1821x over previous
#include <cuda_runtime.h>
#include <cuda_bf16.h>
#include <cstdint>

#define T_STEPS 64
#define N_NODES 20000
#define NTILES_TOT 1250     // 16 nodes per tile, 1 tile per active warp

__device__ float g_scratch[T_STEPS * NTILES_TOT];

__device__ __forceinline__ float tanha(float v) {
    float r; asm("tanh.approx.f32 %0, %1;" : "=f"(r) : "f"(v)); return r;
}
__device__ __forceinline__ float sigm(float v) { return fmaf(0.5f, tanha(0.5f * v), 0.5f); }
__device__ __forceinline__ float lrelu(float v) { return fmaxf(v, 0.01f * v); }
__device__ __forceinline__ uint32_t tf(float v) {
    uint32_t r; asm("cvt.rna.tf32.f32 %0, %1;" : "=r"(r) : "f"(v)); return r;
}
__device__ __forceinline__ void mmatf(float* c, const uint32_t* a, uint32_t b0, uint32_t b1) {
    asm volatile("mma.sync.aligned.m16n8k8.row.col.f32.tf32.tf32.f32 "
        "{%0,%1,%2,%3}, {%4,%5,%6,%7}, {%8,%9}, {%0,%1,%2,%3};"
        : "+f"(c[0]), "+f"(c[1]), "+f"(c[2]), "+f"(c[3])
        : "r"(a[0]), "r"(a[1]), "r"(a[2]), "r"(a[3]), "r"(b0), "r"(b1));
}

// tf32 weights in smem, conflict-free strides (words mod 32 distinct per warp access)
__shared__ uint32_t sW1[96 * 44];   // [n=96][k=44]: k0-7 Wx*, k8-39 Wh{z,r} (cand rows 0)
__shared__ uint32_t sW2[32 * 36];   // [n=32][k=36]: Whh^T

// transpose C-layout pair registers -> tf32 A-fragment for one k8 block.
// src arrays v0 (row m), v1 (row m+8) hold dims 2l+{0,1}+8*blk; thread needs dims l, l+4.
__device__ __forceinline__ void h2a(const float* v0, const float* v1, int B,
                                    int o1, int o2, bool ls, uint32_t* A) {
    float p00 = __shfl_sync(0xffffffffu, v0[2*B],   o1);
    float p01 = __shfl_sync(0xffffffffu, v0[2*B+1], o1);
    float p10 = __shfl_sync(0xffffffffu, v1[2*B],   o1);
    float p11 = __shfl_sync(0xffffffffu, v1[2*B+1], o1);
    float q00 = __shfl_sync(0xffffffffu, v0[2*B],   o2);
    float q01 = __shfl_sync(0xffffffffu, v0[2*B+1], o2);
    float q10 = __shfl_sync(0xffffffffu, v1[2*B],   o2);
    float q11 = __shfl_sync(0xffffffffu, v1[2*B+1], o2);
    A[0] = tf(ls ? p01 : p00);   // (row m,   k=l)
    A[1] = tf(ls ? p11 : p10);   // (row m+8, k=l)
    A[2] = tf(ls ? q01 : q00);   // (row m,   k=l+4)
    A[3] = tf(ls ? q11 : q10);   // (row m+8, k=l+4)
}

__device__ void run_tile(int tile,
    const float* __restrict__ x, const float* __restrict__ h0,
    const float* __restrict__ W1, float b1s, const float* __restrict__ W2,
    const float* __restrict__ bxz, const float* __restrict__ bhz,
    const float* __restrict__ bxr, const float* __restrict__ bhr,
    const float* __restrict__ bxh, const float* __restrict__ bhh,
    float* __restrict__ out, int out_size, int lane)
{
    const int l = lane & 3, g = lane >> 2;
    const int o1 = (lane & 28) | (l >> 1), o2 = o1 + 2;
    const bool ls = l & 1;

    float w1s[8];
#pragma unroll
    for (int s = 0; s < 8; s++) w1s[s] = W1[2 * l + 8 * (s >> 1) + (s & 1)];

    float bC[12][2];
#pragma unroll
    for (int jj = 0; jj < 4; jj++)
#pragma unroll
        for (int e = 0; e < 2; e++) {
            int n = 8 * jj + 2 * l + e;
            bC[jj][e]     = bxz[n] + bhz[n];
            bC[jj + 4][e] = bxr[n] + bhr[n];
            bC[jj + 8][e] = bxh[n] + bhh[n];
        }

    const int n0 = tile * 16 + g;
    const int n1 = n0 + 8;
    float h[2][8];
#pragma unroll
    for (int s = 0; s < 8; s++) {
        int d = 2 * l + 8 * (s >> 1) + (s & 1);
        h[0][s] = h0[n0 * 32 + d];
        h[1][s] = h0[n1 * 32 + d];
    }
    const float w2a = W2[n0], w2b = W2[n1];

#pragma unroll 1
    for (int t = 0; t < T_STEPS; ++t) {
        // ---- x A-fragment (K=8): direct element loads, no relayout needed ----
        const float* xb = x + (size_t)t * (N_NODES * 8);
        uint32_t Ax[4];
        Ax[0] = tf(xb[(size_t)n0 * 8 + l]);
        Ax[1] = tf(xb[(size_t)n1 * 8 + l]);
        Ax[2] = tf(xb[(size_t)n0 * 8 + l + 4]);
        Ax[3] = tf(xb[(size_t)n1 * 8 + l + 4]);
        // ---- h A-fragments (4 k8 chunks) via shuffle transpose ----
        uint32_t Ah[4][4];
#pragma unroll
        for (int B = 0; B < 4; B++) h2a(h[0], h[1], B, o1, o2, ls, Ah[B]);

        // ---- MMA1: 12 n-tiles, single-pass tf32 ----
        float zz[2][8], gg[2][8], candC[4][4];
#pragma unroll
        for (int j = 0; j < 12; j++) {
            float C[4] = {bC[j][0], bC[j][1], bC[j][0], bC[j][1]};
            const uint32_t* wr = &sW1[(8 * j + g) * 44];
            mmatf(C, Ax, wr[l], wr[l + 4]);
            if (j < 8) {
#pragma unroll
                for (int c = 0; c < 4; c++)
                    mmatf(C, Ah[c], wr[8 + 8 * c + l], wr[8 + 8 * c + l + 4]);
            }
            if (j < 4) {
                zz[0][2*j] = sigm(C[0]); zz[0][2*j+1] = sigm(C[1]);
                zz[1][2*j] = sigm(C[2]); zz[1][2*j+1] = sigm(C[3]);
            } else if (j < 8) {
                int jj = j - 4;
                gg[0][2*jj]   = h[0][2*jj]   * sigm(C[0]);
                gg[0][2*jj+1] = h[0][2*jj+1] * sigm(C[1]);
                gg[1][2*jj]   = h[1][2*jj]   * sigm(C[2]);
                gg[1][2*jj+1] = h[1][2*jj+1] * sigm(C[3]);
            } else {
#pragma unroll
                for (int e = 0; e < 4; e++) candC[j - 8][e] = C[e];
            }
        }

        // ---- gg -> A-fragments, MMA2 into candC ----
        uint32_t Ag[4][4];
#pragma unroll
        for (int B = 0; B < 4; B++) h2a(gg[0], gg[1], B, o1, o2, ls, Ag[B]);
#pragma unroll
        for (int j = 0; j < 4; j++) {
            const uint32_t* wr = &sW2[(8 * j + g) * 36];
#pragma unroll
            for (int c = 0; c < 4; c++)
                mmatf(candC[j], Ag[c], wr[8 * c + l], wr[8 * c + l + 4]);
        }

        // ---- update + fused readout (C-layout, unchanged) ----
        float p0 = 0.f, p1 = 0.f;
#pragma unroll
        for (int j = 0; j < 4; j++) {
            float t00 = tanha(candC[j][0]), t01 = tanha(candC[j][1]);
            float t10 = tanha(candC[j][2]), t11 = tanha(candC[j][3]);
            float hn;
            hn = t00 + zz[0][2*j]   * (h[0][2*j]   - t00); h[0][2*j]   = hn; p0 = fmaf(lrelu(hn), w1s[2*j],   p0);
            hn = t01 + zz[0][2*j+1] * (h[0][2*j+1] - t01); h[0][2*j+1] = hn; p0 = fmaf(lrelu(hn), w1s[2*j+1], p0);
            hn = t10 + zz[1][2*j]   * (h[1][2*j]   - t10); h[1][2*j]   = hn; p1 = fmaf(lrelu(hn), w1s[2*j],   p1);
            hn = t11 + zz[1][2*j+1] * (h[1][2*j+1] - t11); h[1][2*j+1] = hn; p1 = fmaf(lrelu(hn), w1s[2*j+1], p1);
        }
        p0 += __shfl_xor_sync(0xffffffffu, p0, 1);
        p0 += __shfl_xor_sync(0xffffffffu, p0, 2);
        p1 += __shfl_xor_sync(0xffffffffu, p1, 1);
        p1 += __shfl_xor_sync(0xffffffffu, p1, 2);
        float st = lrelu(p0 + b1s) * w2a + lrelu(p1 + b1s) * w2b;
        st += __shfl_xor_sync(0xffffffffu, st, 4);
        st += __shfl_xor_sync(0xffffffffu, st, 8);
        st += __shfl_xor_sync(0xffffffffu, st, 16);
        if (lane == 0) g_scratch[t * NTILES_TOT + tile] = st;
    }

    if (out_size >= N_NODES * 32) {
        const int hoff = out_size - N_NODES * 32;
#pragma unroll
        for (int j = 0; j < 4; j++) {
            *(float2*)(out + hoff + n0 * 32 + 2 * l + 8 * j) = make_float2(h[0][2*j], h[0][2*j+1]);
            *(float2*)(out + hoff + n1 * 32 + 2 * l + 8 * j) = make_float2(h[1][2*j], h[1][2*j+1]);
        }
    }
}

__global__ void __launch_bounds__(320, 1)
gru_mma(const float* __restrict__ x, const float* __restrict__ h0,
        const float* __restrict__ Wxz, const float* __restrict__ bxz,
        const float* __restrict__ Whz, const float* __restrict__ bhz,
        const float* __restrict__ Wxr, const float* __restrict__ bxr,
        const float* __restrict__ Whr, const float* __restrict__ bhr,
        const float* __restrict__ Wxh, const float* __restrict__ bxh,
        const float* __restrict__ Whh, const float* __restrict__ bhh,
        const float* __restrict__ W1,  const float* __restrict__ b1,
        const float* __restrict__ W2,
        float* __restrict__ out, int out_size)
{
    const int tid = threadIdx.x, b = blockIdx.x;
    // stage W1 [n=96][k=44] as tf32 bits
    for (int i = tid; i < 96 * 44; i += 320) {
        int n = i / 44, k = i % 44;
        float v = 0.f;
        if (k < 8) v = (n < 32) ? Wxz[k*32+n] : (n < 64) ? Wxr[k*32+n-32] : Wxh[k*32+n-64];
        else if (k < 40) {
            int kk = k - 8;
            v = (n < 32) ? Whz[kk*32+n] : (n < 64) ? Whr[kk*32+n-32] : 0.f;
        }
        sW1[i] = tf(v);
    }
    // stage W2 [n=32][k=36] = Whh^T as tf32 bits
    for (int i = tid; i < 32 * 36; i += 320) {
        int n = i / 36, k = i % 36;
        sW2[i] = tf((k < 32) ? Whh[k*32+n] : 0.f);
    }
    __syncthreads();

    const int w = tid >> 5, lane = tid & 31;
    const float b1s = b1[0];

    // blocks 0..65: 9 active warps; blocks 66..147: 8 active warps. Total 1250.
    const int nact = (b < 66) ? 9 : 8;
    if (w < nact) {
        const int tile = (b < 66) ? (9 * b + w) : (594 + 8 * (b - 66) + w);
        run_tile(tile, x, h0, W1, b1s, W2, bxz, bhz, bxr, bhr, bxh, bhh,
                 out, out_size, lane);
    }
}

__global__ void reduce_out(const float* __restrict__ b2,
                           float* __restrict__ out, int out_size)
{
    const int t = blockIdx.x;
    float s = 0.f;
    for (int w = threadIdx.x; w < NTILES_TOT; w += 256) s += g_scratch[t * NTILES_TOT + w];
#pragma unroll
    for (int o = 16; o; o >>= 1) s += __shfl_xor_sync(0xffffffffu, s, o);
    __shared__ float red[8];
    if ((threadIdx.x & 31) == 0) red[threadIdx.x >> 5] = s;
    __syncthreads();
    if (threadIdx.x < 8) {
        s = red[threadIdx.x];
#pragma unroll
        for (int o = 4; o; o >>= 1) s += __shfl_xor_sync(0x000000ffu, s, o);
        if (threadIdx.x == 0) {
            bool wr = (out_size >= T_STEPS + N_NODES * 32) || (out_size < N_NODES * 32);
            if (wr && t < out_size) out[t] = s + b2[0];
        }
    }
}

extern "C" void kernel_launch(void* const* d_in, const int* in_sizes, int n_in,
                              void* d_out, int out_size) {
    const float* x   = (const float*)d_in[0];
    const float* h0  = (const float*)d_in[3];
    const float* Wxz = (const float*)d_in[4];
    const float* bxz = (const float*)d_in[5];
    const float* Whz = (const float*)d_in[6];
    const float* bhz = (const float*)d_in[7];
    const float* Wxr = (const float*)d_in[8];
    const float* bxr = (const float*)d_in[9];
    const float* Whr = (const float*)d_in[10];
    const float* bhr = (const float*)d_in[11];
    const float* Wxh = (const float*)d_in[12];
    const float* bxh = (const float*)d_in[13];
    const float* Whh = (const float*)d_in[14];
    const float* bhh = (const float*)d_in[15];
    const float* W1  = (const float*)d_in[16];
    const float* b1  = (const float*)d_in[17];
    const float* W2  = (const float*)d_in[18];
    const float* b2  = (const float*)d_in[19];
    float* out = (float*)d_out;

    gru_mma<<<148, 320>>>(x, h0, Wxz, bxz, Whz, bhz, Wxr, bxr, Whr, bhr,
                          Wxh, bxh, Whh, bhh, W1, b1, W2, out, out_size);
    reduce_out<<<T_STEPS, 256>>>(b2, out, out_size);
}